// round 1
// baseline (speedup 1.0000x reference)
#include <cuda_runtime.h>
#include <math.h>
#include <stdint.h>

#define BB 4
#define SS 2048
#define DD 1024
#define NH 16
#define HDIM 64
#define MROWS (BB*SS)   /* 8192 */

// Scratch (allocs are forbidden; __device__ globals are the sanctioned path)
__device__ float g_q[MROWS*DD];
__device__ float g_k[MROWS*DD];
__device__ float g_v[MROWS*DD];
__device__ float g_ctx[MROWS*DD];

// ---------------------------------------------------------------------------
// SGEMM: C[M,N] = A[M,K] @ B[K,N] (+ bias), all row-major fp32.
// 128x128 block, BK=8, 256 threads, 8x8 per-thread microtile (4+4 split).
// ---------------------------------------------------------------------------
__global__ __launch_bounds__(256, 2)
void sgemm_kernel(const float* __restrict__ A, const float* __restrict__ Bm,
                  const float* __restrict__ bias, float* __restrict__ C,
                  int M, int N, int K)
{
    __shared__ float As[8][132];   // padded: conflict-free transposed stores
    __shared__ float Bs[8][128];

    const int t  = threadIdx.x;
    const int m0 = blockIdx.y * 128;
    const int n0 = blockIdx.x * 128;
    const int ty = t >> 4;         // 0..15
    const int tx = t & 15;         // 0..15

    const int arow = t >> 1, akk = (t & 1) * 4;
    const int bkk  = t >> 5, bcol = (t & 31) * 4;

    float acc[8][8];
#pragma unroll
    for (int i = 0; i < 8; i++)
#pragma unroll
        for (int j = 0; j < 8; j++) acc[i][j] = 0.f;

    for (int k0 = 0; k0 < K; k0 += 8) {
        // prefetch into registers before the barrier
        const float4 av = *(const float4*)(A  + (size_t)(m0 + arow) * K + k0 + akk);
        const float4 bv = *(const float4*)(Bm + (size_t)(k0 + bkk) * N + n0 + bcol);
        __syncthreads();           // previous compute done reading shared
        As[akk+0][arow] = av.x;
        As[akk+1][arow] = av.y;
        As[akk+2][arow] = av.z;
        As[akk+3][arow] = av.w;
        *(float4*)&Bs[bkk][bcol] = bv;
        __syncthreads();

#pragma unroll
        for (int kk = 0; kk < 8; kk++) {
            float a[8], b[8];
            *(float4*)(a)     = *(const float4*)&As[kk][ty*4];
            *(float4*)(a + 4) = *(const float4*)&As[kk][64 + ty*4];
            *(float4*)(b)     = *(const float4*)&Bs[kk][tx*4];
            *(float4*)(b + 4) = *(const float4*)&Bs[kk][64 + tx*4];
#pragma unroll
            for (int i = 0; i < 8; i++)
#pragma unroll
                for (int j = 0; j < 8; j++)
                    acc[i][j] += a[i] * b[j];
        }
    }

#pragma unroll
    for (int i = 0; i < 8; i++) {
        const int row = m0 + ((i < 4) ? (ty*4 + i) : (64 + ty*4 + (i - 4)));
#pragma unroll
        for (int jh = 0; jh < 2; jh++) {
            const int col = n0 + jh*64 + tx*4;
            float4 o;
            o.x = acc[i][jh*4+0];
            o.y = acc[i][jh*4+1];
            o.z = acc[i][jh*4+2];
            o.w = acc[i][jh*4+3];
            if (bias) {
                o.x += bias[col+0];
                o.y += bias[col+1];
                o.z += bias[col+2];
                o.w += bias[col+3];
            }
            *(float4*)(C + (size_t)row * N + col) = o;
        }
    }
}

// ---------------------------------------------------------------------------
// Causal flash attention, fp32. One CTA = one (b, h, 64-query block).
// 256 threads = 64 rows x 4-lane quads; quad owns j = c + 4*jj (jj=0..15)
// of the 64-wide key tile and output cols {16g + 4c} as float4s.
// Shared: q, k, v, p tiles, each 64 x 68 floats (LD=68 -> conflict-free).
// ---------------------------------------------------------------------------
#define FLD 68
#define FLASH_SMEM (4 * 64 * FLD * (int)sizeof(float))

__global__ __launch_bounds__(256)
void flash_kernel(const float* __restrict__ Q, const float* __restrict__ K,
                  const float* __restrict__ V, float* __restrict__ O)
{
    extern __shared__ float sm[];
    float* q_sh = sm;
    float* k_sh = sm + 64*FLD;
    float* v_sh = sm + 2*64*FLD;
    float* p_sh = sm + 3*64*FLD;

    const int tid = threadIdx.x;
    const int qb = blockIdx.x, h = blockIdx.y, b = blockIdx.z;
    const int r = tid >> 2;     // query row in tile (0..63)
    const int c = tid & 3;      // quad lane

    const float NEG_INF = __int_as_float(0xff800000u);

    const float* Qb  = Q + ((size_t)(b*SS) + qb*64) * DD + h*HDIM;
    const float* Kb0 = K + (size_t)(b*SS) * DD + h*HDIM;
    const float* Vb0 = V + (size_t)(b*SS) * DD + h*HDIM;

    // load q tile (coalesced float4)
#pragma unroll
    for (int i = 0; i < 4; i++) {
        const int idx = tid + 256*i;            // 0..1023
        const int row = idx >> 4;
        const int c4  = (idx & 15) << 2;
        *(float4*)(q_sh + row*FLD + c4) = *(const float4*)(Qb + (size_t)row*DD + c4);
    }

    float m = NEG_INF, l = 0.f;
    float4 acc0 = make_float4(0,0,0,0);
    float4 acc1 = acc0, acc2 = acc0, acc3 = acc0;

    for (int kb = 0; kb <= qb; kb++) {
        const float* Kb = Kb0 + (size_t)(kb*64) * DD;
        const float* Vb = Vb0 + (size_t)(kb*64) * DD;
        __syncthreads();                        // tiles free to overwrite
#pragma unroll
        for (int i = 0; i < 4; i++) {
            const int idx = tid + 256*i;
            const int row = idx >> 4;
            const int c4  = (idx & 15) << 2;
            *(float4*)(k_sh + row*FLD + c4) = *(const float4*)(Kb + (size_t)row*DD + c4);
            *(float4*)(v_sh + row*FLD + c4) = *(const float4*)(Vb + (size_t)row*DD + c4);
        }
        __syncthreads();

        // scores: s[jj] = q[r] . k[c + 4*jj]
        float s[16];
#pragma unroll
        for (int jj = 0; jj < 16; jj++) s[jj] = 0.f;
        for (int d4 = 0; d4 < 16; d4++) {
            const float4 q4 = *(const float4*)(q_sh + r*FLD + 4*d4);
#pragma unroll
            for (int jj = 0; jj < 16; jj++) {
                const float4 k4 = *(const float4*)(k_sh + (c + 4*jj)*FLD + 4*d4);
                s[jj] += q4.x*k4.x + q4.y*k4.y + q4.z*k4.z + q4.w*k4.w;
            }
        }

        // scale + causal mask (diagonal tile only) + local max
        const bool diag = (kb == qb);
        float mloc = NEG_INF;
#pragma unroll
        for (int jj = 0; jj < 16; jj++) {
            const int j = c + 4*jj;
            float sv = s[jj] * 0.125f;          // 1/sqrt(64)
            if (diag && j > r) sv = NEG_INF;
            s[jj] = sv;
            mloc = fmaxf(mloc, sv);
        }
        mloc = fmaxf(mloc, __shfl_xor_sync(0xffffffffu, mloc, 1));
        mloc = fmaxf(mloc, __shfl_xor_sync(0xffffffffu, mloc, 2));

        const float mnew  = fmaxf(m, mloc);
        const float alpha = __expf(m - mnew);   // 0 on first tile (m = -inf)

        float lloc = 0.f;
#pragma unroll
        for (int jj = 0; jj < 16; jj++) {
            const float p = __expf(s[jj] - mnew);
            p_sh[r*FLD + c + 4*jj] = p;
            lloc += p;
        }
        lloc += __shfl_xor_sync(0xffffffffu, lloc, 1);
        lloc += __shfl_xor_sync(0xffffffffu, lloc, 2);
        l = l * alpha + lloc;
        m = mnew;

        acc0.x *= alpha; acc0.y *= alpha; acc0.z *= alpha; acc0.w *= alpha;
        acc1.x *= alpha; acc1.y *= alpha; acc1.z *= alpha; acc1.w *= alpha;
        acc2.x *= alpha; acc2.y *= alpha; acc2.z *= alpha; acc2.w *= alpha;
        acc3.x *= alpha; acc3.y *= alpha; acc3.z *= alpha; acc3.w *= alpha;

        __syncwarp();                           // p row written by own quad only

        // acc += p @ v
#pragma unroll 4
        for (int j = 0; j < 64; j++) {
            const float pv = p_sh[r*FLD + j];
            const float4 v0 = *(const float4*)(v_sh + j*FLD +  0 + 4*c);
            const float4 v1 = *(const float4*)(v_sh + j*FLD + 16 + 4*c);
            const float4 v2 = *(const float4*)(v_sh + j*FLD + 32 + 4*c);
            const float4 v3 = *(const float4*)(v_sh + j*FLD + 48 + 4*c);
            acc0.x += pv*v0.x; acc0.y += pv*v0.y; acc0.z += pv*v0.z; acc0.w += pv*v0.w;
            acc1.x += pv*v1.x; acc1.y += pv*v1.y; acc1.z += pv*v1.z; acc1.w += pv*v1.w;
            acc2.x += pv*v2.x; acc2.y += pv*v2.y; acc2.z += pv*v2.z; acc2.w += pv*v2.w;
            acc3.x += pv*v3.x; acc3.y += pv*v3.y; acc3.z += pv*v3.z; acc3.w += pv*v3.w;
        }
    }

    const float inv = 1.f / l;
    float* Ob = O + ((size_t)(b*SS) + qb*64) * DD + h*HDIM;
    float4 o;
    o = acc0; o.x*=inv; o.y*=inv; o.z*=inv; o.w*=inv;
    *(float4*)(Ob + (size_t)r*DD +  0 + 4*c) = o;
    o = acc1; o.x*=inv; o.y*=inv; o.z*=inv; o.w*=inv;
    *(float4*)(Ob + (size_t)r*DD + 16 + 4*c) = o;
    o = acc2; o.x*=inv; o.y*=inv; o.z*=inv; o.w*=inv;
    *(float4*)(Ob + (size_t)r*DD + 32 + 4*c) = o;
    o = acc3; o.x*=inv; o.y*=inv; o.z*=inv; o.w*=inv;
    *(float4*)(Ob + (size_t)r*DD + 48 + 4*c) = o;
}

// ---------------------------------------------------------------------------
extern "C" void kernel_launch(void* const* d_in, const int* in_sizes, int n_in,
                              void* d_out, int out_size)
{
    const float* x  = (const float*)d_in[0];
    const float* Wq = (const float*)d_in[1];
    const float* Wk = (const float*)d_in[2];
    const float* Wv = (const float*)d_in[3];
    const float* Wo = (const float*)d_in[4];
    const float* bo = (const float*)d_in[5];
    float* out = (float*)d_out;

    float *q, *k, *v, *ctx;
    cudaGetSymbolAddress((void**)&q,   g_q);
    cudaGetSymbolAddress((void**)&k,   g_k);
    cudaGetSymbolAddress((void**)&v,   g_v);
    cudaGetSymbolAddress((void**)&ctx, g_ctx);

    dim3 gg(DD / 128, MROWS / 128);   // (8, 64)
    sgemm_kernel<<<gg, 256>>>(x, Wq, nullptr, q, MROWS, DD, DD);
    sgemm_kernel<<<gg, 256>>>(x, Wk, nullptr, k, MROWS, DD, DD);
    sgemm_kernel<<<gg, 256>>>(x, Wv, nullptr, v, MROWS, DD, DD);

    cudaFuncSetAttribute(flash_kernel,
                         cudaFuncAttributeMaxDynamicSharedMemorySize, FLASH_SMEM);
    dim3 gf(SS / 64, NH, BB);         // (32, 16, 4)
    flash_kernel<<<gf, 256, FLASH_SMEM>>>(q, k, v, ctx);

    sgemm_kernel<<<gg, 256>>>(ctx, Wo, bo, out, MROWS, DD, DD);
}

// round 4
// speedup vs baseline: 2.4747x; 2.4747x over previous
#include <cuda_runtime.h>
#include <cuda_bf16.h>
#include <cuda_fp16.h>
#include <math.h>
#include <stdint.h>

#define BB 4
#define SS 2048
#define DD 1024
#define NH 16
#define HDIM 64
#define MROWS (BB*SS)   /* 8192 */

typedef __nv_bfloat16 bf16;

// ---------------- scratch (__device__ globals; allocs forbidden) ------------
__device__ bf16  g_xhi[MROWS*DD];
__device__ bf16  g_xlo[MROWS*DD];
__device__ bf16  g_qhi[MROWS*DD];
__device__ bf16  g_qlo[MROWS*DD];
__device__ bf16  g_khi[MROWS*DD];
__device__ bf16  g_klo[MROWS*DD];
__device__ __half g_vh[MROWS*DD];
__device__ bf16  g_chi[MROWS*DD];
__device__ bf16  g_clo[MROWS*DD];
// transposed+split weights: [0]=Wq_hi [1]=Wq_lo [2]=Wk_hi [3]=Wk_lo
//                           [4]=Wv_hi [5]=Wv_lo [6]=Wo_hi [7]=Wo_lo
__device__ bf16  g_wt[8][DD*DD];

// ---------------- mma wrappers ----------------------------------------------
static __device__ __forceinline__ void mma_bf16(float* c, const uint32_t* a,
                                                const uint32_t* b) {
    asm volatile(
        "mma.sync.aligned.m16n8k16.row.col.f32.bf16.bf16.f32 "
        "{%0,%1,%2,%3}, {%4,%5,%6,%7}, {%8,%9}, {%0,%1,%2,%3};"
        : "+f"(c[0]), "+f"(c[1]), "+f"(c[2]), "+f"(c[3])
        : "r"(a[0]), "r"(a[1]), "r"(a[2]), "r"(a[3]), "r"(b[0]), "r"(b[1]));
}
static __device__ __forceinline__ void mma_f16(float* c, const uint32_t* a,
                                               const uint32_t* b) {
    asm volatile(
        "mma.sync.aligned.m16n8k16.row.col.f32.f16.f16.f32 "
        "{%0,%1,%2,%3}, {%4,%5,%6,%7}, {%8,%9}, {%0,%1,%2,%3};"
        : "+f"(c[0]), "+f"(c[1]), "+f"(c[2]), "+f"(c[3])
        : "r"(a[0]), "r"(a[1]), "r"(a[2]), "r"(a[3]), "r"(b[0]), "r"(b[1]));
}
static __device__ __forceinline__ uint32_t h2_as_u32(__half2 v) {
    union { __half2 h; uint32_t u; } cvt;
    cvt.h = v;
    return cvt.u;
}

// ---------------- split / transpose kernels ---------------------------------
__global__ void fsplit_kernel(const float4* __restrict__ x,
                              __nv_bfloat162* __restrict__ hi,
                              __nv_bfloat162* __restrict__ lo, int n4)
{
    int i = blockIdx.x * blockDim.x + threadIdx.x;
    if (i >= n4) return;
    float4 v = x[i];
    bf16 h0 = __float2bfloat16(v.x), h1 = __float2bfloat16(v.y);
    bf16 h2 = __float2bfloat16(v.z), h3 = __float2bfloat16(v.w);
    __nv_bfloat162 a, b, c, d;
    a.x = h0; a.y = h1; b.x = h2; b.y = h3;
    c.x = __float2bfloat16(v.x - __bfloat162float(h0));
    c.y = __float2bfloat16(v.y - __bfloat162float(h1));
    d.x = __float2bfloat16(v.z - __bfloat162float(h2));
    d.y = __float2bfloat16(v.w - __bfloat162float(h3));
    hi[2*i] = a; hi[2*i+1] = b;
    lo[2*i] = c; lo[2*i+1] = d;
}

__global__ void wsplit_kernel(const float* __restrict__ W,
                              bf16* __restrict__ thi, bf16* __restrict__ tlo)
{
    __shared__ float t[32][33];
    const int n0 = blockIdx.x * 32, k0 = blockIdx.y * 32;
    const int tx = threadIdx.x, ty = threadIdx.y;   // 32 x 8
#pragma unroll
    for (int i = 0; i < 32; i += 8)
        t[ty + i][tx] = W[(size_t)(k0 + ty + i) * DD + n0 + tx];
    __syncthreads();
#pragma unroll
    for (int i = 0; i < 32; i += 8) {
        float v = t[tx][ty + i];                    // W[k0+tx][n0+ty+i]
        bf16 h = __float2bfloat16(v);
        float r = v - __bfloat162float(h);
        size_t o = (size_t)(n0 + ty + i) * DD + k0 + tx;  // WT[n][k]
        thi[o] = h;
        tlo[o] = __float2bfloat16(r);
    }
}

// ---------------- mma.sync bf16 split GEMM -----------------------------------
// C[8192,1024] = A[8192,1024] @ WT[1024,1024]^T, 3-term bf16 split, f32 accum.
// CTA 128x128, BK=32, 8 warps (warp tile 64x32), double-buffered smem.
// MODE 0: f32 + bias -> outF;  1: bf16 hi/lo -> outHi/outLo;  2: fp16 -> outH.
#define ALD 40          /* smem row stride (bf16) */
#define NCHUNK 96       /* 3 terms x 32 chunks of K=32 */

template<int MODE>
__global__ __launch_bounds__(256)
void gemm_mma(const bf16* __restrict__ Ahi, const bf16* __restrict__ Alo,
              const bf16* __restrict__ Bhi, const bf16* __restrict__ Blo,
              const float* __restrict__ bias,
              float* __restrict__ outF, bf16* __restrict__ outHi,
              bf16* __restrict__ outLo, __half* __restrict__ outH)
{
    __shared__ bf16 As[2][128*ALD];
    __shared__ bf16 Bs[2][128*ALD];

    const int t = threadIdx.x;
    const int wid = t >> 5, lane = t & 31;
    const int wm = wid & 1, wn = wid >> 1;      // 2 x 4 warp grid
    const int g = lane >> 2, qd = lane & 3;
    const int qd2 = qd * 2;
    const int m0 = blockIdx.y * 128, n0 = blockIdx.x * 128;

    const bf16* Aterm[3] = {Ahi, Ahi, Alo};
    const bf16* Bterm[3] = {Bhi, Blo, Bhi};

    const int grow = t >> 1;             // 0..127
    const int gq   = (t & 1) * 16;       // 0 or 16

    float acc[4][4][4];
#pragma unroll
    for (int i = 0; i < 4; i++)
#pragma unroll
        for (int j = 0; j < 4; j++)
#pragma unroll
            for (int e = 0; e < 4; e++) acc[i][j][e] = 0.f;

    // preload chunk 0
    {
        const bf16* A = Aterm[0];
        const bf16* B = Bterm[0];
        const uint4 a0 = *(const uint4*)(A + (size_t)(m0 + grow) * DD + gq);
        const uint4 a1 = *(const uint4*)(A + (size_t)(m0 + grow) * DD + gq + 8);
        const uint4 b0 = *(const uint4*)(B + (size_t)(n0 + grow) * DD + gq);
        const uint4 b1 = *(const uint4*)(B + (size_t)(n0 + grow) * DD + gq + 8);
        *(uint4*)&As[0][grow*ALD + gq]     = a0;
        *(uint4*)&As[0][grow*ALD + gq + 8] = a1;
        *(uint4*)&Bs[0][grow*ALD + gq]     = b0;
        *(uint4*)&Bs[0][grow*ALD + gq + 8] = b1;
    }
    __syncthreads();

    for (int c = 0; c < NCHUNK; c++) {
        const int st = c & 1;
        uint4 ra0, ra1, rb0, rb1;
        if (c + 1 < NCHUNK) {
            const int term = (c + 1) >> 5;
            const int kc = ((c + 1) & 31) * 32;
            const bf16* A = Aterm[term];
            const bf16* B = Bterm[term];
            ra0 = *(const uint4*)(A + (size_t)(m0 + grow) * DD + kc + gq);
            ra1 = *(const uint4*)(A + (size_t)(m0 + grow) * DD + kc + gq + 8);
            rb0 = *(const uint4*)(B + (size_t)(n0 + grow) * DD + kc + gq);
            rb1 = *(const uint4*)(B + (size_t)(n0 + grow) * DD + kc + gq + 8);
        }

#pragma unroll
        for (int kk = 0; kk < 32; kk += 16) {
            uint32_t a[4][4], b[4][2];
#pragma unroll
            for (int i = 0; i < 4; i++) {
                const int r = wm*64 + i*16 + g;
                a[i][0] = *(const uint32_t*)&As[st][(r    )*ALD + kk + qd2];
                a[i][1] = *(const uint32_t*)&As[st][(r + 8)*ALD + kk + qd2];
                a[i][2] = *(const uint32_t*)&As[st][(r    )*ALD + kk + qd2 + 8];
                a[i][3] = *(const uint32_t*)&As[st][(r + 8)*ALD + kk + qd2 + 8];
            }
#pragma unroll
            for (int j = 0; j < 4; j++) {
                const int n = wn*32 + j*8 + g;
                b[j][0] = *(const uint32_t*)&Bs[st][n*ALD + kk + qd2];
                b[j][1] = *(const uint32_t*)&Bs[st][n*ALD + kk + qd2 + 8];
            }
#pragma unroll
            for (int i = 0; i < 4; i++)
#pragma unroll
                for (int j = 0; j < 4; j++)
                    mma_bf16(acc[i][j], a[i], b[j]);
        }
        __syncthreads();
        if (c + 1 < NCHUNK) {
            const int so = st ^ 1;
            *(uint4*)&As[so][grow*ALD + gq]     = ra0;
            *(uint4*)&As[so][grow*ALD + gq + 8] = ra1;
            *(uint4*)&Bs[so][grow*ALD + gq]     = rb0;
            *(uint4*)&Bs[so][grow*ALD + gq + 8] = rb1;
        }
        __syncthreads();
    }

    // epilogue
#pragma unroll
    for (int i = 0; i < 4; i++) {
        const int r1 = m0 + wm*64 + i*16 + g;
        const int r2 = r1 + 8;
#pragma unroll
        for (int j = 0; j < 4; j++) {
            const int col = n0 + wn*32 + j*8 + qd2;
            const float v0 = acc[i][j][0], v1 = acc[i][j][1];
            const float v2 = acc[i][j][2], v3 = acc[i][j][3];
            if (MODE == 0) {
                float2 o1, o2;
                o1.x = v0 + bias[col]; o1.y = v1 + bias[col+1];
                o2.x = v2 + bias[col]; o2.y = v3 + bias[col+1];
                *(float2*)(outF + (size_t)r1 * DD + col) = o1;
                *(float2*)(outF + (size_t)r2 * DD + col) = o2;
            } else if (MODE == 1) {
                __nv_bfloat162 h1, l1, h2, l2;
                h1.x = __float2bfloat16(v0); h1.y = __float2bfloat16(v1);
                l1.x = __float2bfloat16(v0 - __bfloat162float(h1.x));
                l1.y = __float2bfloat16(v1 - __bfloat162float(h1.y));
                h2.x = __float2bfloat16(v2); h2.y = __float2bfloat16(v3);
                l2.x = __float2bfloat16(v2 - __bfloat162float(h2.x));
                l2.y = __float2bfloat16(v3 - __bfloat162float(h2.y));
                *(__nv_bfloat162*)(outHi + (size_t)r1 * DD + col) = h1;
                *(__nv_bfloat162*)(outLo + (size_t)r1 * DD + col) = l1;
                *(__nv_bfloat162*)(outHi + (size_t)r2 * DD + col) = h2;
                *(__nv_bfloat162*)(outLo + (size_t)r2 * DD + col) = l2;
            } else {
                *(__half2*)(outH + (size_t)r1 * DD + col) = __floats2half2_rn(v0, v1);
                *(__half2*)(outH + (size_t)r2 * DD + col) = __floats2half2_rn(v2, v3);
            }
        }
    }
}

// ---------------- causal flash attention, mma.sync ---------------------------
// CTA = (qb, h, b): 64 q-rows x 64-key tiles. 128 threads = 4 warps, each
// warp owns 16 q-rows. QK^T: 3-term bf16 split (K'=64 per term). PV: fp16.
// V stored transposed in smem [hd][key].
#define QLD 72

__global__ __launch_bounds__(128)
void flash_mma(const bf16* __restrict__ Qhi, const bf16* __restrict__ Qlo,
               const bf16* __restrict__ Khi, const bf16* __restrict__ Klo,
               const __half* __restrict__ Vh,
               bf16* __restrict__ Chi, bf16* __restrict__ Clo)
{
    __shared__ bf16 sqh[64*QLD], sql[64*QLD];
    __shared__ bf16 skh[64*QLD], skl[64*QLD];
    __shared__ __half sv[64*QLD];               // [hd][key]

    const int t = threadIdx.x;
    const int w = t >> 5, lane = t & 31;
    const int g = lane >> 2, qd = lane & 3;
    const int qd2 = qd * 2;
    const int qb = blockIdx.x, h = blockIdx.y, b = blockIdx.z;

    const size_t qrow0 = (size_t)b * SS + qb * 64;
    const size_t krow0 = (size_t)b * SS;
    const int hc = h * HDIM;

    // load q tiles
#pragma unroll
    for (int i = 0; i < 4; i++) {
        const int idx = t + 128*i;              // 0..511
        const int row = idx >> 3, cq = (idx & 7) * 8;
        *(uint4*)&sqh[row*QLD + cq] = *(const uint4*)(Qhi + (qrow0 + row)*DD + hc + cq);
        *(uint4*)&sql[row*QLD + cq] = *(const uint4*)(Qlo + (qrow0 + row)*DD + hc + cq);
    }

    float sc[8][4];
    float o[8][4];
#pragma unroll
    for (int j = 0; j < 8; j++)
#pragma unroll
        for (int e = 0; e < 4; e++) o[j][e] = 0.f;
    const float NEG_INF = __int_as_float(0xff800000u);
    float m0 = NEG_INF, m1 = NEG_INF, l0 = 0.f, l1 = 0.f;

    const int row_l0 = 16*w + g;                // tile-local q row (c0,c1)
    const int row_l1 = row_l0 + 8;              // (c2,c3)

    for (int kb = 0; kb <= qb; kb++) {
        __syncthreads();
        // load k tiles
#pragma unroll
        for (int i = 0; i < 4; i++) {
            const int idx = t + 128*i;
            const int row = idx >> 3, cq = (idx & 7) * 8;
            const size_t gr = (krow0 + kb*64 + row)*DD + hc + cq;
            *(uint4*)&skh[row*QLD + cq] = *(const uint4*)(Khi + gr);
            *(uint4*)&skl[row*QLD + cq] = *(const uint4*)(Klo + gr);
        }
        // load v transposed: sv[hd][key]
#pragma unroll
        for (int i = 0; i < 4; i++) {
            const int idx = t + 128*i;
            const int key = idx & 63, cq = idx >> 6;    // cq 0..7
            union { uint4 u; __half hx[8]; } ld;
            ld.u = *(const uint4*)(Vh + (krow0 + kb*64 + key)*DD + hc + cq*8);
#pragma unroll
            for (int j = 0; j < 8; j++)
                sv[(cq*8 + j)*QLD + key] = ld.hx[j];
        }
        __syncthreads();

        // ---- scores = q . k  (3-term split) ----
#pragma unroll
        for (int j = 0; j < 8; j++)
#pragma unroll
            for (int e = 0; e < 4; e++) sc[j][e] = 0.f;

        const bf16* qptr[3] = {sqh, sqh, sql};
        const bf16* kptr[3] = {skh, skl, skh};
#pragma unroll
        for (int term = 0; term < 3; term++) {
            const bf16* qs = qptr[term];
            const bf16* ks = kptr[term];
#pragma unroll
            for (int s = 0; s < 4; s++) {       // k' steps of 16
                uint32_t a[4];
                const int kc = s*16 + qd2;
                a[0] = *(const uint32_t*)&qs[(row_l0    )*QLD + kc];
                a[1] = *(const uint32_t*)&qs[(row_l0 + 8)*QLD + kc];
                a[2] = *(const uint32_t*)&qs[(row_l0    )*QLD + kc + 8];
                a[3] = *(const uint32_t*)&qs[(row_l0 + 8)*QLD + kc + 8];
#pragma unroll
                for (int j = 0; j < 8; j++) {
                    uint32_t bfr[2];
                    bfr[0] = *(const uint32_t*)&ks[(j*8 + g)*QLD + kc];
                    bfr[1] = *(const uint32_t*)&ks[(j*8 + g)*QLD + kc + 8];
                    mma_bf16(sc[j], a, bfr);
                }
            }
        }

        // ---- scale + causal mask + online softmax ----
        const bool diag = (kb == qb);
        float mx0 = NEG_INF, mx1 = NEG_INF;
#pragma unroll
        for (int j = 0; j < 8; j++) {
            const int c0 = j*8 + qd2, c1 = c0 + 1;
            float s0 = sc[j][0] * 0.125f, s1 = sc[j][1] * 0.125f;
            float s2 = sc[j][2] * 0.125f, s3 = sc[j][3] * 0.125f;
            if (diag) {
                if (c0 > row_l0) s0 = NEG_INF;
                if (c1 > row_l0) s1 = NEG_INF;
                if (c0 > row_l1) s2 = NEG_INF;
                if (c1 > row_l1) s3 = NEG_INF;
            }
            sc[j][0] = s0; sc[j][1] = s1; sc[j][2] = s2; sc[j][3] = s3;
            mx0 = fmaxf(mx0, fmaxf(s0, s1));
            mx1 = fmaxf(mx1, fmaxf(s2, s3));
        }
        mx0 = fmaxf(mx0, __shfl_xor_sync(0xffffffffu, mx0, 1));
        mx0 = fmaxf(mx0, __shfl_xor_sync(0xffffffffu, mx0, 2));
        mx1 = fmaxf(mx1, __shfl_xor_sync(0xffffffffu, mx1, 1));
        mx1 = fmaxf(mx1, __shfl_xor_sync(0xffffffffu, mx1, 2));

        const float mn0 = fmaxf(m0, mx0), mn1 = fmaxf(m1, mx1);
        const float al0 = __expf(m0 - mn0), al1 = __expf(m1 - mn1);
        m0 = mn0; m1 = mn1;

        float s0sum = 0.f, s1sum = 0.f;
#pragma unroll
        for (int j = 0; j < 8; j++) {
            const float p0 = __expf(sc[j][0] - mn0);
            const float p1 = __expf(sc[j][1] - mn0);
            const float p2 = __expf(sc[j][2] - mn1);
            const float p3 = __expf(sc[j][3] - mn1);
            sc[j][0] = p0; sc[j][1] = p1; sc[j][2] = p2; sc[j][3] = p3;
            s0sum += p0 + p1; s1sum += p2 + p3;
        }
        s0sum += __shfl_xor_sync(0xffffffffu, s0sum, 1);
        s0sum += __shfl_xor_sync(0xffffffffu, s0sum, 2);
        s1sum += __shfl_xor_sync(0xffffffffu, s1sum, 1);
        s1sum += __shfl_xor_sync(0xffffffffu, s1sum, 2);
        l0 = l0 * al0 + s0sum;
        l1 = l1 * al1 + s1sum;

#pragma unroll
        for (int j = 0; j < 8; j++) {
            o[j][0] *= al0; o[j][1] *= al0;
            o[j][2] *= al1; o[j][3] *= al1;
        }

        // ---- o += P @ V  (fp16) ----
#pragma unroll
        for (int s = 0; s < 4; s++) {           // key steps of 16
            uint32_t a[4];
            a[0] = h2_as_u32(__floats2half2_rn(sc[2*s  ][0], sc[2*s  ][1]));
            a[1] = h2_as_u32(__floats2half2_rn(sc[2*s  ][2], sc[2*s  ][3]));
            a[2] = h2_as_u32(__floats2half2_rn(sc[2*s+1][0], sc[2*s+1][1]));
            a[3] = h2_as_u32(__floats2half2_rn(sc[2*s+1][2], sc[2*s+1][3]));
            const int kc = s*16 + qd2;
#pragma unroll
            for (int j = 0; j < 8; j++) {
                uint32_t bfr[2];
                bfr[0] = *(const uint32_t*)&sv[(j*8 + g)*QLD + kc];
                bfr[1] = *(const uint32_t*)&sv[(j*8 + g)*QLD + kc + 8];
                mma_f16(o[j], a, bfr);
            }
        }
    }

    // ---- epilogue: normalize, split to bf16 hi/lo ----
    const float inv0 = 1.f / l0, inv1 = 1.f / l1;
    const size_t r1 = qrow0 + row_l0;
    const size_t r2 = qrow0 + row_l1;
#pragma unroll
    for (int j = 0; j < 8; j++) {
        const int col = hc + j*8 + qd2;
        const float v0 = o[j][0]*inv0, v1 = o[j][1]*inv0;
        const float v2 = o[j][2]*inv1, v3 = o[j][3]*inv1;
        __nv_bfloat162 h1, lo1, h2, lo2;
        h1.x = __float2bfloat16(v0); h1.y = __float2bfloat16(v1);
        lo1.x = __float2bfloat16(v0 - __bfloat162float(h1.x));
        lo1.y = __float2bfloat16(v1 - __bfloat162float(h1.y));
        h2.x = __float2bfloat16(v2); h2.y = __float2bfloat16(v3);
        lo2.x = __float2bfloat16(v2 - __bfloat162float(h2.x));
        lo2.y = __float2bfloat16(v3 - __bfloat162float(h2.y));
        *(__nv_bfloat162*)(Chi + r1*DD + col) = h1;
        *(__nv_bfloat162*)(Clo + r1*DD + col) = lo1;
        *(__nv_bfloat162*)(Chi + r2*DD + col) = h2;
        *(__nv_bfloat162*)(Clo + r2*DD + col) = lo2;
    }
}

// ---------------------------------------------------------------------------
extern "C" void kernel_launch(void* const* d_in, const int* in_sizes, int n_in,
                              void* d_out, int out_size)
{
    const float* x  = (const float*)d_in[0];
    const float* Wq = (const float*)d_in[1];
    const float* Wk = (const float*)d_in[2];
    const float* Wv = (const float*)d_in[3];
    const float* Wo = (const float*)d_in[4];
    const float* bo = (const float*)d_in[5];
    float* out = (float*)d_out;

    bf16 *xhi, *xlo, *qhi, *qlo, *khi, *klo, *chi, *clo, *wt;
    __half* vh;
    cudaGetSymbolAddress((void**)&xhi, g_xhi);
    cudaGetSymbolAddress((void**)&xlo, g_xlo);
    cudaGetSymbolAddress((void**)&qhi, g_qhi);
    cudaGetSymbolAddress((void**)&qlo, g_qlo);
    cudaGetSymbolAddress((void**)&khi, g_khi);
    cudaGetSymbolAddress((void**)&klo, g_klo);
    cudaGetSymbolAddress((void**)&vh,  g_vh);
    cudaGetSymbolAddress((void**)&chi, g_chi);
    cudaGetSymbolAddress((void**)&clo, g_clo);
    cudaGetSymbolAddress((void**)&wt,  g_wt);
    bf16* w[8];
    for (int i = 0; i < 8; i++) w[i] = wt + (size_t)i * DD * DD;

    // weight transpose + split
    dim3 wb(32, 8), wg(DD/32, DD/32);
    wsplit_kernel<<<wg, wb>>>(Wq, w[0], w[1]);
    wsplit_kernel<<<wg, wb>>>(Wk, w[2], w[3]);
    wsplit_kernel<<<wg, wb>>>(Wv, w[4], w[5]);
    wsplit_kernel<<<wg, wb>>>(Wo, w[6], w[7]);

    // x split
    const int n4 = MROWS * DD / 4;
    fsplit_kernel<<<n4 / 256, 256>>>((const float4*)x,
                                     (__nv_bfloat162*)xhi, (__nv_bfloat162*)xlo, n4);

    // projections (tensor cores via mma.sync)
    dim3 gg(DD / 128, MROWS / 128);   // (8, 64)
    gemm_mma<1><<<gg, 256>>>(xhi, xlo, w[0], w[1], nullptr,
                             nullptr, qhi, qlo, nullptr);
    gemm_mma<1><<<gg, 256>>>(xhi, xlo, w[2], w[3], nullptr,
                             nullptr, khi, klo, nullptr);
    gemm_mma<2><<<gg, 256>>>(xhi, xlo, w[4], w[5], nullptr,
                             nullptr, nullptr, nullptr, vh);

    // attention
    dim3 gf(SS / 64, NH, BB);         // (32, 16, 4)
    flash_mma<<<gf, 128>>>(qhi, qlo, khi, klo, vh, chi, clo);

    // output projection + bias
    gemm_mma<0><<<gg, 256>>>(chi, clo, w[6], w[7], bo,
                             out, nullptr, nullptr, nullptr);
}

// round 5
// speedup vs baseline: 3.4823x; 1.4072x over previous
#include <cuda_runtime.h>
#include <cuda_bf16.h>
#include <cuda_fp16.h>
#include <math.h>
#include <stdint.h>

#define BB 4
#define SS 2048
#define DD 1024
#define NH 16
#define HDIM 64
#define MROWS (BB*SS)   /* 8192 */

typedef __nv_bfloat16 bf16;

// ---------------- scratch (__device__ globals; allocs forbidden) ------------
__device__ bf16  g_xhi[MROWS*DD];
__device__ bf16  g_xlo[MROWS*DD];
__device__ bf16  g_qhi[MROWS*DD];
__device__ bf16  g_qlo[MROWS*DD];
__device__ bf16  g_khi[MROWS*DD];
__device__ bf16  g_klo[MROWS*DD];
__device__ __half g_vh[MROWS*DD];
__device__ bf16  g_chi[MROWS*DD];
__device__ bf16  g_clo[MROWS*DD];
__device__ bf16  g_wt[8][DD*DD];   // [Wq_hi,Wq_lo,Wk_hi,Wk_lo,Wv_hi,Wv_lo,Wo_hi,Wo_lo]

// ---------------- ptx helpers -------------------------------------------------
static __device__ __forceinline__ void mma_bf16(float* c, const uint32_t* a,
                                                const uint32_t* b) {
    asm volatile(
        "mma.sync.aligned.m16n8k16.row.col.f32.bf16.bf16.f32 "
        "{%0,%1,%2,%3}, {%4,%5,%6,%7}, {%8,%9}, {%0,%1,%2,%3};"
        : "+f"(c[0]), "+f"(c[1]), "+f"(c[2]), "+f"(c[3])
        : "r"(a[0]), "r"(a[1]), "r"(a[2]), "r"(a[3]), "r"(b[0]), "r"(b[1]));
}
static __device__ __forceinline__ void mma_f16(float* c, const uint32_t* a,
                                               const uint32_t* b) {
    asm volatile(
        "mma.sync.aligned.m16n8k16.row.col.f32.f16.f16.f32 "
        "{%0,%1,%2,%3}, {%4,%5,%6,%7}, {%8,%9}, {%0,%1,%2,%3};"
        : "+f"(c[0]), "+f"(c[1]), "+f"(c[2]), "+f"(c[3])
        : "r"(a[0]), "r"(a[1]), "r"(a[2]), "r"(a[3]), "r"(b[0]), "r"(b[1]));
}
static __device__ __forceinline__ void ldsm4(uint32_t* r, uint32_t a) {
    asm volatile("ldmatrix.sync.aligned.m8n8.x4.shared.b16 {%0,%1,%2,%3}, [%4];"
                 : "=r"(r[0]), "=r"(r[1]), "=r"(r[2]), "=r"(r[3]) : "r"(a));
}
static __device__ __forceinline__ void ldsm4t(uint32_t* r, uint32_t a) {
    asm volatile("ldmatrix.sync.aligned.m8n8.x4.trans.shared.b16 {%0,%1,%2,%3}, [%4];"
                 : "=r"(r[0]), "=r"(r[1]), "=r"(r[2]), "=r"(r[3]) : "r"(a));
}
static __device__ __forceinline__ uint32_t s2u(const void* p) {
    uint32_t a;
    asm("{ .reg .u64 t; cvta.to.shared.u64 t, %1; cvt.u32.u64 %0, t; }"
        : "=r"(a) : "l"(p));
    return a;
}
static __device__ __forceinline__ void cpa16(uint32_t dst, const void* src) {
    asm volatile("cp.async.cg.shared.global [%0], [%1], 16;"
                 :: "r"(dst), "l"(src));
}
static __device__ __forceinline__ void cp_commit() {
    asm volatile("cp.async.commit_group;");
}
template<int N>
static __device__ __forceinline__ void cp_wait() {
    asm volatile("cp.async.wait_group %0;" :: "n"(N));
}
static __device__ __forceinline__ uint32_t h2_as_u32(__half2 v) {
    union { __half2 h; uint32_t u; } cvt;
    cvt.h = v;
    return cvt.u;
}

// ---------------- split / transpose kernels ---------------------------------
__global__ void fsplit_kernel(const float4* __restrict__ x,
                              __nv_bfloat162* __restrict__ hi,
                              __nv_bfloat162* __restrict__ lo, int n4)
{
    int i = blockIdx.x * blockDim.x + threadIdx.x;
    if (i >= n4) return;
    float4 v = x[i];
    bf16 h0 = __float2bfloat16(v.x), h1 = __float2bfloat16(v.y);
    bf16 h2 = __float2bfloat16(v.z), h3 = __float2bfloat16(v.w);
    __nv_bfloat162 a, b, c, d;
    a.x = h0; a.y = h1; b.x = h2; b.y = h3;
    c.x = __float2bfloat16(v.x - __bfloat162float(h0));
    c.y = __float2bfloat16(v.y - __bfloat162float(h1));
    d.x = __float2bfloat16(v.z - __bfloat162float(h2));
    d.y = __float2bfloat16(v.w - __bfloat162float(h3));
    hi[2*i] = a; hi[2*i+1] = b;
    lo[2*i] = c; lo[2*i+1] = d;
}

__global__ void wsplit_kernel(const float* __restrict__ W,
                              bf16* __restrict__ thi, bf16* __restrict__ tlo)
{
    __shared__ float t[32][33];
    const int n0 = blockIdx.x * 32, k0 = blockIdx.y * 32;
    const int tx = threadIdx.x, ty = threadIdx.y;   // 32 x 8
#pragma unroll
    for (int i = 0; i < 32; i += 8)
        t[ty + i][tx] = W[(size_t)(k0 + ty + i) * DD + n0 + tx];
    __syncthreads();
#pragma unroll
    for (int i = 0; i < 32; i += 8) {
        float v = t[tx][ty + i];
        bf16 h = __float2bfloat16(v);
        float r = v - __bfloat162float(h);
        size_t o = (size_t)(n0 + ty + i) * DD + k0 + tx;
        thi[o] = h;
        tlo[o] = __float2bfloat16(r);
    }
}

// ---------------- mma.sync bf16 split GEMM -----------------------------------
// C[8192,1024] = A @ WT^T, 3-term bf16 split, f32 accum. CTA 128x128, BK=32,
// 8 warps (64x32 each), cp.async double-buffer, ldmatrix fragments.
#define ALD 40
#define NCHUNK 96

template<int MODE>
__global__ __launch_bounds__(256)
void gemm_mma(const bf16* __restrict__ Ahi, const bf16* __restrict__ Alo,
              const bf16* __restrict__ Bhi, const bf16* __restrict__ Blo,
              const float* __restrict__ bias,
              float* __restrict__ outF, bf16* __restrict__ outHi,
              bf16* __restrict__ outLo, __half* __restrict__ outH)
{
    __shared__ bf16 As[2][128*ALD];
    __shared__ bf16 Bs[2][128*ALD];
    const uint32_t asu = s2u(As), bsu = s2u(Bs);

    const int t = threadIdx.x;
    const int wid = t >> 5, lane = t & 31;
    const int wm = wid & 1, wn = wid >> 1;
    const int g = lane >> 2, qd = lane & 3;
    const int qd2 = qd * 2;
    const int m0 = blockIdx.y * 128, n0 = blockIdx.x * 128;

    const bf16* Aterm[3] = {Ahi, Ahi, Alo};
    const bf16* Bterm[3] = {Bhi, Blo, Bhi};

    // cp.async mapping: 2 sweeps of 256 threads x 16B per matrix per chunk
    const int ld_row = t >> 2;             // 0..63 (+64 on sweep 2)
    const int ld_col = (t & 3) * 8;

    // ldmatrix lane offsets
    const int a_r = wm*64 + (lane & 15);
    const int a_c = (lane >> 4) * 8;
    const int b_r = wn*32 + (lane & 7) + ((lane >> 4) << 3);
    const int b_c = ((lane >> 3) & 1) * 8;

    float acc[4][4][4];
#pragma unroll
    for (int i = 0; i < 4; i++)
#pragma unroll
        for (int j = 0; j < 4; j++)
#pragma unroll
            for (int e = 0; e < 4; e++) acc[i][j][e] = 0.f;

    auto issue = [&](int c, int st) {
        const int term = c >> 5;
        const int kc = (c & 31) * 32;
        const bf16* A = Aterm[term];
        const bf16* B = Bterm[term];
#pragma unroll
        for (int i = 0; i < 2; i++) {
            const int row = ld_row + i*64;
            const uint32_t so = (uint32_t)(st*128*ALD + row*ALD + ld_col) * 2;
            cpa16(asu + so, A + (size_t)(m0 + row) * DD + kc + ld_col);
            cpa16(bsu + so, B + (size_t)(n0 + row) * DD + kc + ld_col);
        }
        cp_commit();
    };

    issue(0, 0);

    for (int c = 0; c < NCHUNK; c++) {
        const int st = c & 1;
        if (c + 1 < NCHUNK) { issue(c + 1, st ^ 1); cp_wait<1>(); }
        else                { cp_wait<0>(); }
        __syncthreads();

        const uint32_t ab = asu + (uint32_t)(st*128*ALD)*2;
        const uint32_t bb = bsu + (uint32_t)(st*128*ALD)*2;
#pragma unroll
        for (int s = 0; s < 2; s++) {
            uint32_t a[4][4], b4[2][4];
#pragma unroll
            for (int i = 0; i < 4; i++)
                ldsm4(a[i], ab + (uint32_t)((a_r + i*16)*ALD + s*16 + a_c)*2);
#pragma unroll
            for (int jp = 0; jp < 2; jp++)
                ldsm4(b4[jp], bb + (uint32_t)((b_r + jp*16)*ALD + s*16 + b_c)*2);
#pragma unroll
            for (int i = 0; i < 4; i++)
#pragma unroll
                for (int j = 0; j < 4; j++)
                    mma_bf16(acc[i][j], a[i], &b4[j >> 1][(j & 1) * 2]);
        }
        __syncthreads();
    }

    // epilogue
#pragma unroll
    for (int i = 0; i < 4; i++) {
        const int r1 = m0 + wm*64 + i*16 + g;
        const int r2 = r1 + 8;
#pragma unroll
        for (int j = 0; j < 4; j++) {
            const int col = n0 + wn*32 + j*8 + qd2;
            const float v0 = acc[i][j][0], v1 = acc[i][j][1];
            const float v2 = acc[i][j][2], v3 = acc[i][j][3];
            if (MODE == 0) {
                float2 o1, o2;
                o1.x = v0 + bias[col]; o1.y = v1 + bias[col+1];
                o2.x = v2 + bias[col]; o2.y = v3 + bias[col+1];
                *(float2*)(outF + (size_t)r1 * DD + col) = o1;
                *(float2*)(outF + (size_t)r2 * DD + col) = o2;
            } else if (MODE == 1) {
                __nv_bfloat162 h1, l1, h2, l2;
                h1.x = __float2bfloat16(v0); h1.y = __float2bfloat16(v1);
                l1.x = __float2bfloat16(v0 - __bfloat162float(h1.x));
                l1.y = __float2bfloat16(v1 - __bfloat162float(h1.y));
                h2.x = __float2bfloat16(v2); h2.y = __float2bfloat16(v3);
                l2.x = __float2bfloat16(v2 - __bfloat162float(h2.x));
                l2.y = __float2bfloat16(v3 - __bfloat162float(h2.y));
                *(__nv_bfloat162*)(outHi + (size_t)r1 * DD + col) = h1;
                *(__nv_bfloat162*)(outLo + (size_t)r1 * DD + col) = l1;
                *(__nv_bfloat162*)(outHi + (size_t)r2 * DD + col) = h2;
                *(__nv_bfloat162*)(outLo + (size_t)r2 * DD + col) = l2;
            } else {
                *(__half2*)(outH + (size_t)r1 * DD + col) = __floats2half2_rn(v0, v1);
                *(__half2*)(outH + (size_t)r2 * DD + col) = __floats2half2_rn(v2, v3);
            }
        }
    }
}

// ---------------- causal flash attention, mma.sync + cp.async ----------------
// CTA = (qb, h, b): 128 q-rows x 64-key tiles, 256 threads (8 warps x 16 rows).
// Q in registers (one ldmatrix pass); K via ldmatrix, V via ldmatrix.trans.
#define FLD 72
#define Q_BYTES (128*FLD*2)                 /* 18432 */
#define ST_ONE  (64*FLD*2)                  /* 9216  */
#define ST_BYTES (3*ST_ONE)                 /* 27648 */
#define FLASH_SMEM (2*Q_BYTES + 2*ST_BYTES) /* 92160 */

__global__ __launch_bounds__(256)
void flash_mma(const bf16* __restrict__ Qhi, const bf16* __restrict__ Qlo,
               const bf16* __restrict__ Khi, const bf16* __restrict__ Klo,
               const __half* __restrict__ Vh,
               bf16* __restrict__ Chi, bf16* __restrict__ Clo)
{
    extern __shared__ char smc[];
    const uint32_t smu = s2u(smc);
    const uint32_t qh_u = smu, ql_u = smu + Q_BYTES;
    const uint32_t st_u = smu + 2*Q_BYTES;

    const int t = threadIdx.x;
    const int w = t >> 5, lane = t & 31;
    const int g = lane >> 2, qd = lane & 3;
    const int qd2 = qd * 2;
    const int qb = (gridDim.x - 1) - blockIdx.x;   // heavy tiles first
    const int h = blockIdx.y, b = blockIdx.z;

    const size_t qrow0 = (size_t)b * SS + qb * 128;
    const size_t krow0 = (size_t)b * SS;
    const int hc = h * HDIM;
    const int kbmax = 2*qb + 1;

    // ldmatrix lane offsets
    const int qa_r = 16*w + (lane & 15);
    const int qa_c = (lane >> 4) * 8;
    const int kb_r = (lane & 7) + ((lane >> 4) << 3);
    const int kb_c = ((lane >> 3) & 1) * 8;
    const int v_r  = (lane & 7) + (((lane >> 3) & 1) << 3);
    const int v_c  = (lane >> 4) * 8;

    // ---- prologue: Q (group 0) + K/V tile 0 (group 1) ----
#pragma unroll
    for (int i = 0; i < 4; i++) {
        const int idx = t + 256*i;
        const int row = idx >> 3, col = (idx & 7) * 8;
        const uint32_t so = (uint32_t)(row*FLD + col) * 2;
        cpa16(qh_u + so, Qhi + (qrow0 + row)*DD + hc + col);
        cpa16(ql_u + so, Qlo + (qrow0 + row)*DD + hc + col);
    }
    cp_commit();

    auto issue_kv = [&](int kb, int st) {
        const uint32_t sb = st_u + st*ST_BYTES;
#pragma unroll
        for (int i = 0; i < 2; i++) {
            const int idx = t + 256*i;
            const int row = idx >> 3, col = (idx & 7) * 8;
            const uint32_t so = (uint32_t)(row*FLD + col) * 2;
            const size_t gr = (krow0 + kb*64 + row)*DD + hc + col;
            cpa16(sb + so,            Khi + gr);
            cpa16(sb + ST_ONE + so,   Klo + gr);
            cpa16(sb + 2*ST_ONE + so, Vh  + gr);
        }
        cp_commit();
    };
    issue_kv(0, 0);

    cp_wait<1>();                      // Q arrived
    __syncthreads();

    uint32_t qa_h[4][4], qa_l[4][4];
#pragma unroll
    for (int s = 0; s < 4; s++) {
        ldsm4(qa_h[s], qh_u + (uint32_t)(qa_r*FLD + s*16 + qa_c)*2);
        ldsm4(qa_l[s], ql_u + (uint32_t)(qa_r*FLD + s*16 + qa_c)*2);
    }

    float sc[8][4], o[8][4];
#pragma unroll
    for (int j = 0; j < 8; j++)
#pragma unroll
        for (int e = 0; e < 4; e++) o[j][e] = 0.f;
    const float NEG_INF = __int_as_float(0xff800000u);
    float m0 = NEG_INF, m1 = NEG_INF, l0 = 0.f, l1 = 0.f;

    const int grow0 = qb*128 + 16*w + g;     // global q row (c0,c1)
    const int grow1 = grow0 + 8;             // (c2,c3)

    for (int kb = 0; kb <= kbmax; kb++) {
        const int st = kb & 1;
        if (kb + 1 <= kbmax) { issue_kv(kb + 1, st ^ 1); cp_wait<1>(); }
        else                 { cp_wait<0>(); }
        __syncthreads();

        const uint32_t skh = st_u + st*ST_BYTES;
        const uint32_t skl = skh + ST_ONE;
        const uint32_t svb = skh + 2*ST_ONE;

        // ---- scores (3-term split) ----
#pragma unroll
        for (int j = 0; j < 8; j++)
#pragma unroll
            for (int e = 0; e < 4; e++) sc[j][e] = 0.f;

#pragma unroll
        for (int s = 0; s < 4; s++) {
#pragma unroll
            for (int jp = 0; jp < 4; jp++) {
                uint32_t bh[4], bl[4];
                const uint32_t off = (uint32_t)((jp*16 + kb_r)*FLD + s*16 + kb_c)*2;
                ldsm4(bh, skh + off);
                ldsm4(bl, skl + off);
                mma_bf16(sc[2*jp  ], qa_h[s], bh);
                mma_bf16(sc[2*jp+1], qa_h[s], bh + 2);
                mma_bf16(sc[2*jp  ], qa_h[s], bl);
                mma_bf16(sc[2*jp+1], qa_h[s], bl + 2);
                mma_bf16(sc[2*jp  ], qa_l[s], bh);
                mma_bf16(sc[2*jp+1], qa_l[s], bh + 2);
            }
        }

        // ---- scale + causal mask + online softmax ----
        const bool diag = (kb >= 2*qb);
        float mx0 = NEG_INF, mx1 = NEG_INF;
#pragma unroll
        for (int j = 0; j < 8; j++) {
            const int c0 = kb*64 + j*8 + qd2, c1 = c0 + 1;
            float s0 = sc[j][0]*0.125f, s1 = sc[j][1]*0.125f;
            float s2 = sc[j][2]*0.125f, s3 = sc[j][3]*0.125f;
            if (diag) {
                if (c0 > grow0) s0 = NEG_INF;
                if (c1 > grow0) s1 = NEG_INF;
                if (c0 > grow1) s2 = NEG_INF;
                if (c1 > grow1) s3 = NEG_INF;
            }
            sc[j][0] = s0; sc[j][1] = s1; sc[j][2] = s2; sc[j][3] = s3;
            mx0 = fmaxf(mx0, fmaxf(s0, s1));
            mx1 = fmaxf(mx1, fmaxf(s2, s3));
        }
        mx0 = fmaxf(mx0, __shfl_xor_sync(0xffffffffu, mx0, 1));
        mx0 = fmaxf(mx0, __shfl_xor_sync(0xffffffffu, mx0, 2));
        mx1 = fmaxf(mx1, __shfl_xor_sync(0xffffffffu, mx1, 1));
        mx1 = fmaxf(mx1, __shfl_xor_sync(0xffffffffu, mx1, 2));

        const float mn0 = fmaxf(m0, mx0), mn1 = fmaxf(m1, mx1);
        const float al0 = __expf(m0 - mn0), al1 = __expf(m1 - mn1);
        m0 = mn0; m1 = mn1;

        float s0sum = 0.f, s1sum = 0.f;
#pragma unroll
        for (int j = 0; j < 8; j++) {
            const float p0 = __expf(sc[j][0] - mn0);
            const float p1 = __expf(sc[j][1] - mn0);
            const float p2 = __expf(sc[j][2] - mn1);
            const float p3 = __expf(sc[j][3] - mn1);
            sc[j][0] = p0; sc[j][1] = p1; sc[j][2] = p2; sc[j][3] = p3;
            s0sum += p0 + p1; s1sum += p2 + p3;
        }
        s0sum += __shfl_xor_sync(0xffffffffu, s0sum, 1);
        s0sum += __shfl_xor_sync(0xffffffffu, s0sum, 2);
        s1sum += __shfl_xor_sync(0xffffffffu, s1sum, 1);
        s1sum += __shfl_xor_sync(0xffffffffu, s1sum, 2);
        l0 = l0 * al0 + s0sum;
        l1 = l1 * al1 + s1sum;

#pragma unroll
        for (int j = 0; j < 8; j++) {
            o[j][0] *= al0; o[j][1] *= al0;
            o[j][2] *= al1; o[j][3] *= al1;
        }

        // ---- o += P @ V  (fp16, V via ldmatrix.trans) ----
#pragma unroll
        for (int s = 0; s < 4; s++) {
            uint32_t a[4];
            a[0] = h2_as_u32(__floats2half2_rn(sc[2*s  ][0], sc[2*s  ][1]));
            a[1] = h2_as_u32(__floats2half2_rn(sc[2*s  ][2], sc[2*s  ][3]));
            a[2] = h2_as_u32(__floats2half2_rn(sc[2*s+1][0], sc[2*s+1][1]));
            a[3] = h2_as_u32(__floats2half2_rn(sc[2*s+1][2], sc[2*s+1][3]));
#pragma unroll
            for (int jp = 0; jp < 4; jp++) {
                uint32_t bv[4];
                ldsm4t(bv, svb + (uint32_t)((s*16 + v_r)*FLD + jp*16 + v_c)*2);
                mma_f16(o[2*jp  ], a, bv);
                mma_f16(o[2*jp+1], a, bv + 2);
            }
        }
        __syncthreads();
    }

    // ---- epilogue: normalize, split to bf16 hi/lo ----
    const float inv0 = 1.f / l0, inv1 = 1.f / l1;
    const size_t r1 = qrow0 + 16*w + g;
    const size_t r2 = r1 + 8;
#pragma unroll
    for (int j = 0; j < 8; j++) {
        const int col = hc + j*8 + qd2;
        const float v0 = o[j][0]*inv0, v1 = o[j][1]*inv0;
        const float v2 = o[j][2]*inv1, v3 = o[j][3]*inv1;
        __nv_bfloat162 h1, lo1, h2, lo2;
        h1.x = __float2bfloat16(v0); h1.y = __float2bfloat16(v1);
        lo1.x = __float2bfloat16(v0 - __bfloat162float(h1.x));
        lo1.y = __float2bfloat16(v1 - __bfloat162float(h1.y));
        h2.x = __float2bfloat16(v2); h2.y = __float2bfloat16(v3);
        lo2.x = __float2bfloat16(v2 - __bfloat162float(h2.x));
        lo2.y = __float2bfloat16(v3 - __bfloat162float(h2.y));
        *(__nv_bfloat162*)(Chi + r1*DD + col) = h1;
        *(__nv_bfloat162*)(Clo + r1*DD + col) = lo1;
        *(__nv_bfloat162*)(Chi + r2*DD + col) = h2;
        *(__nv_bfloat162*)(Clo + r2*DD + col) = lo2;
    }
}

// ---------------------------------------------------------------------------
extern "C" void kernel_launch(void* const* d_in, const int* in_sizes, int n_in,
                              void* d_out, int out_size)
{
    const float* x  = (const float*)d_in[0];
    const float* Wq = (const float*)d_in[1];
    const float* Wk = (const float*)d_in[2];
    const float* Wv = (const float*)d_in[3];
    const float* Wo = (const float*)d_in[4];
    const float* bo = (const float*)d_in[5];
    float* out = (float*)d_out;

    bf16 *xhi, *xlo, *qhi, *qlo, *khi, *klo, *chi, *clo, *wt;
    __half* vh;
    cudaGetSymbolAddress((void**)&xhi, g_xhi);
    cudaGetSymbolAddress((void**)&xlo, g_xlo);
    cudaGetSymbolAddress((void**)&qhi, g_qhi);
    cudaGetSymbolAddress((void**)&qlo, g_qlo);
    cudaGetSymbolAddress((void**)&khi, g_khi);
    cudaGetSymbolAddress((void**)&klo, g_klo);
    cudaGetSymbolAddress((void**)&vh,  g_vh);
    cudaGetSymbolAddress((void**)&chi, g_chi);
    cudaGetSymbolAddress((void**)&clo, g_clo);
    cudaGetSymbolAddress((void**)&wt,  g_wt);
    bf16* w[8];
    for (int i = 0; i < 8; i++) w[i] = wt + (size_t)i * DD * DD;

    cudaFuncSetAttribute(flash_mma,
                         cudaFuncAttributeMaxDynamicSharedMemorySize, FLASH_SMEM);

    // weight transpose + split
    dim3 wb(32, 8), wg(DD/32, DD/32);
    wsplit_kernel<<<wg, wb>>>(Wq, w[0], w[1]);
    wsplit_kernel<<<wg, wb>>>(Wk, w[2], w[3]);
    wsplit_kernel<<<wg, wb>>>(Wv, w[4], w[5]);
    wsplit_kernel<<<wg, wb>>>(Wo, w[6], w[7]);

    // x split
    const int n4 = MROWS * DD / 4;
    fsplit_kernel<<<n4 / 256, 256>>>((const float4*)x,
                                     (__nv_bfloat162*)xhi, (__nv_bfloat162*)xlo, n4);

    // projections
    dim3 gg(DD / 128, MROWS / 128);   // (8, 64)
    gemm_mma<1><<<gg, 256>>>(xhi, xlo, w[0], w[1], nullptr,
                             nullptr, qhi, qlo, nullptr);
    gemm_mma<1><<<gg, 256>>>(xhi, xlo, w[2], w[3], nullptr,
                             nullptr, khi, klo, nullptr);
    gemm_mma<2><<<gg, 256>>>(xhi, xlo, w[4], w[5], nullptr,
                             nullptr, nullptr, nullptr, vh);

    // attention
    dim3 gf(SS / 128, NH, BB);        // (16, 16, 4)
    flash_mma<<<gf, 256, FLASH_SMEM>>>(qhi, qlo, khi, klo, vh, chi, clo);

    // output projection + bias
    gemm_mma<0><<<gg, 256>>>(chi, clo, w[6], w[7], bo,
                             out, nullptr, nullptr, nullptr);
}

// round 6
// speedup vs baseline: 4.0413x; 1.1605x over previous
#include <cuda_runtime.h>
#include <cuda_bf16.h>
#include <cuda_fp16.h>
#include <math.h>
#include <stdint.h>

#define BB 4
#define SS 2048
#define DD 1024
#define NH 16
#define HDIM 64
#define MROWS (BB*SS)   /* 8192 */

typedef __nv_bfloat16 bf16;

// ---------------- scratch (__device__ globals; allocs forbidden) ------------
__device__ bf16  g_xhi[MROWS*DD];
__device__ bf16  g_xlo[MROWS*DD];
__device__ bf16  g_qhi[MROWS*DD];
__device__ bf16  g_qlo[MROWS*DD];
__device__ bf16  g_khi[MROWS*DD];
__device__ bf16  g_klo[MROWS*DD];
__device__ __half g_vh[MROWS*DD];
__device__ bf16  g_chi[MROWS*DD];
__device__ bf16  g_clo[MROWS*DD];
__device__ bf16  g_wt[8][DD*DD];   // [Wq_hi,Wq_lo,Wk_hi,Wk_lo,Wv_hi,Wv_lo,Wo_hi,Wo_lo]

// ---------------- ptx helpers -------------------------------------------------
static __device__ __forceinline__ void mma_bf16(float* c, const uint32_t* a,
                                                const uint32_t* b) {
    asm volatile(
        "mma.sync.aligned.m16n8k16.row.col.f32.bf16.bf16.f32 "
        "{%0,%1,%2,%3}, {%4,%5,%6,%7}, {%8,%9}, {%0,%1,%2,%3};"
        : "+f"(c[0]), "+f"(c[1]), "+f"(c[2]), "+f"(c[3])
        : "r"(a[0]), "r"(a[1]), "r"(a[2]), "r"(a[3]), "r"(b[0]), "r"(b[1]));
}
static __device__ __forceinline__ void mma_f16(float* c, const uint32_t* a,
                                               const uint32_t* b) {
    asm volatile(
        "mma.sync.aligned.m16n8k16.row.col.f32.f16.f16.f32 "
        "{%0,%1,%2,%3}, {%4,%5,%6,%7}, {%8,%9}, {%0,%1,%2,%3};"
        : "+f"(c[0]), "+f"(c[1]), "+f"(c[2]), "+f"(c[3])
        : "r"(a[0]), "r"(a[1]), "r"(a[2]), "r"(a[3]), "r"(b[0]), "r"(b[1]));
}
static __device__ __forceinline__ void ldsm4(uint32_t* r, uint32_t a) {
    asm volatile("ldmatrix.sync.aligned.m8n8.x4.shared.b16 {%0,%1,%2,%3}, [%4];"
                 : "=r"(r[0]), "=r"(r[1]), "=r"(r[2]), "=r"(r[3]) : "r"(a));
}
static __device__ __forceinline__ void ldsm4t(uint32_t* r, uint32_t a) {
    asm volatile("ldmatrix.sync.aligned.m8n8.x4.trans.shared.b16 {%0,%1,%2,%3}, [%4];"
                 : "=r"(r[0]), "=r"(r[1]), "=r"(r[2]), "=r"(r[3]) : "r"(a));
}
static __device__ __forceinline__ uint32_t s2u(const void* p) {
    uint32_t a;
    asm("{ .reg .u64 t; cvta.to.shared.u64 t, %1; cvt.u32.u64 %0, t; }"
        : "=r"(a) : "l"(p));
    return a;
}
static __device__ __forceinline__ void cpa16(uint32_t dst, const void* src) {
    asm volatile("cp.async.cg.shared.global [%0], [%1], 16;"
                 :: "r"(dst), "l"(src));
}
static __device__ __forceinline__ void cp_commit() {
    asm volatile("cp.async.commit_group;");
}
template<int N>
static __device__ __forceinline__ void cp_wait() {
    asm volatile("cp.async.wait_group %0;" :: "n"(N));
}
static __device__ __forceinline__ uint32_t h2_as_u32(__half2 v) {
    union { __half2 h; uint32_t u; } cvt;
    cvt.h = v;
    return cvt.u;
}

// ---------------- split / transpose kernels ---------------------------------
__global__ void fsplit_kernel(const float4* __restrict__ x,
                              __nv_bfloat162* __restrict__ hi,
                              __nv_bfloat162* __restrict__ lo, int n4)
{
    int i = blockIdx.x * blockDim.x + threadIdx.x;
    if (i >= n4) return;
    float4 v = x[i];
    bf16 h0 = __float2bfloat16(v.x), h1 = __float2bfloat16(v.y);
    bf16 h2 = __float2bfloat16(v.z), h3 = __float2bfloat16(v.w);
    __nv_bfloat162 a, b, c, d;
    a.x = h0; a.y = h1; b.x = h2; b.y = h3;
    c.x = __float2bfloat16(v.x - __bfloat162float(h0));
    c.y = __float2bfloat16(v.y - __bfloat162float(h1));
    d.x = __float2bfloat16(v.z - __bfloat162float(h2));
    d.y = __float2bfloat16(v.w - __bfloat162float(h3));
    hi[2*i] = a; hi[2*i+1] = b;
    lo[2*i] = c; lo[2*i+1] = d;
}

// one launch, z selects the weight matrix
__global__ void wsplit4_kernel(const float* __restrict__ W0,
                               const float* __restrict__ W1,
                               const float* __restrict__ W2,
                               const float* __restrict__ W3,
                               bf16* __restrict__ wt)
{
    __shared__ float t[32][33];
    const float* Ws[4] = {W0, W1, W2, W3};
    const int z = blockIdx.z;
    const float* W = Ws[z];
    bf16* thi = wt + (size_t)(2*z)   * DD * DD;
    bf16* tlo = wt + (size_t)(2*z+1) * DD * DD;

    const int n0 = blockIdx.x * 32, k0 = blockIdx.y * 32;
    const int tx = threadIdx.x, ty = threadIdx.y;   // 32 x 8
#pragma unroll
    for (int i = 0; i < 32; i += 8)
        t[ty + i][tx] = W[(size_t)(k0 + ty + i) * DD + n0 + tx];
    __syncthreads();
#pragma unroll
    for (int i = 0; i < 32; i += 8) {
        float v = t[tx][ty + i];
        bf16 h = __float2bfloat16(v);
        float r = v - __bfloat162float(h);
        size_t o = (size_t)(n0 + ty + i) * DD + k0 + tx;
        thi[o] = h;
        tlo[o] = __float2bfloat16(r);
    }
}

// ---------------- mma.sync bf16 split GEMM -----------------------------------
// C[8192,1024] = A @ WT^T, 3-term bf16 split, f32 accum. CTA 128x128, BK=32,
// 8 warps (64x32), 3-stage cp.async ring, ldmatrix fragments, 1 sync/chunk.
#define ALD 40
#define NCHUNK 96
#define GSTAGE 3
#define G_MAT (128*ALD)                       /* elements per matrix stage */
#define GEMM_SMEM (2 * GSTAGE * G_MAT * 2)    /* 61440 bytes */

template<int MODE>
__global__ __launch_bounds__(256, 2)
void gemm_mma(const bf16* __restrict__ Ahi, const bf16* __restrict__ Alo,
              const bf16* __restrict__ Bhi, const bf16* __restrict__ Blo,
              const float* __restrict__ bias,
              float* __restrict__ outF, bf16* __restrict__ outHi,
              bf16* __restrict__ outLo, __half* __restrict__ outH)
{
    extern __shared__ char smg[];
    const uint32_t asu = s2u(smg);
    const uint32_t bsu = asu + GSTAGE * G_MAT * 2;

    const int t = threadIdx.x;
    const int wid = t >> 5, lane = t & 31;
    const int wm = wid & 1, wn = wid >> 1;
    const int g = lane >> 2, qd = lane & 3;
    const int qd2 = qd * 2;
    const int m0 = blockIdx.y * 128, n0 = blockIdx.x * 128;

    const bf16* Aterm[3] = {Ahi, Ahi, Alo};
    const bf16* Bterm[3] = {Bhi, Blo, Bhi};

    const int ld_row = t >> 2;
    const int ld_col = (t & 3) * 8;

    const int a_r = wm*64 + (lane & 15);
    const int a_c = (lane >> 4) * 8;
    const int b_r = wn*32 + (lane & 7) + ((lane >> 4) << 3);
    const int b_c = ((lane >> 3) & 1) * 8;

    float acc[4][4][4];
#pragma unroll
    for (int i = 0; i < 4; i++)
#pragma unroll
        for (int j = 0; j < 4; j++)
#pragma unroll
            for (int e = 0; e < 4; e++) acc[i][j][e] = 0.f;

    auto issue = [&](int c) {
        const int st = c % GSTAGE;
        const int term = c >> 5;
        const int kc = (c & 31) * 32;
        const bf16* A = Aterm[term];
        const bf16* B = Bterm[term];
#pragma unroll
        for (int i = 0; i < 2; i++) {
            const int row = ld_row + i*64;
            const uint32_t so = (uint32_t)(st*G_MAT + row*ALD + ld_col) * 2;
            cpa16(asu + so, A + (size_t)(m0 + row) * DD + kc + ld_col);
            cpa16(bsu + so, B + (size_t)(n0 + row) * DD + kc + ld_col);
        }
        cp_commit();
    };

    issue(0);
    issue(1);

    for (int c = 0; c < NCHUNK; c++) {
        const int st = c % GSTAGE;
        if (c == NCHUNK - 1) cp_wait<0>();
        else                 cp_wait<1>();
        __syncthreads();

        const uint32_t ab = asu + (uint32_t)(st*G_MAT)*2;
        const uint32_t bb = bsu + (uint32_t)(st*G_MAT)*2;
#pragma unroll
        for (int s = 0; s < 2; s++) {
            uint32_t a[4][4], b4[2][4];
#pragma unroll
            for (int i = 0; i < 4; i++)
                ldsm4(a[i], ab + (uint32_t)((a_r + i*16)*ALD + s*16 + a_c)*2);
#pragma unroll
            for (int jp = 0; jp < 2; jp++)
                ldsm4(b4[jp], bb + (uint32_t)((b_r + jp*16)*ALD + s*16 + b_c)*2);
#pragma unroll
            for (int i = 0; i < 4; i++)
#pragma unroll
                for (int j = 0; j < 4; j++)
                    mma_bf16(acc[i][j], a[i], &b4[j >> 1][(j & 1) * 2]);
        }
        if (c + 2 < NCHUNK) issue(c + 2);   // writes stage (c-1)%3: retired
    }

    // epilogue
#pragma unroll
    for (int i = 0; i < 4; i++) {
        const int r1 = m0 + wm*64 + i*16 + g;
        const int r2 = r1 + 8;
#pragma unroll
        for (int j = 0; j < 4; j++) {
            const int col = n0 + wn*32 + j*8 + qd2;
            const float v0 = acc[i][j][0], v1 = acc[i][j][1];
            const float v2 = acc[i][j][2], v3 = acc[i][j][3];
            if (MODE == 0) {
                float2 o1, o2;
                o1.x = v0 + bias[col]; o1.y = v1 + bias[col+1];
                o2.x = v2 + bias[col]; o2.y = v3 + bias[col+1];
                *(float2*)(outF + (size_t)r1 * DD + col) = o1;
                *(float2*)(outF + (size_t)r2 * DD + col) = o2;
            } else if (MODE == 1) {
                __nv_bfloat162 h1, l1, h2, l2;
                h1.x = __float2bfloat16(v0); h1.y = __float2bfloat16(v1);
                l1.x = __float2bfloat16(v0 - __bfloat162float(h1.x));
                l1.y = __float2bfloat16(v1 - __bfloat162float(h1.y));
                h2.x = __float2bfloat16(v2); h2.y = __float2bfloat16(v3);
                l2.x = __float2bfloat16(v2 - __bfloat162float(h2.x));
                l2.y = __float2bfloat16(v3 - __bfloat162float(h2.y));
                *(__nv_bfloat162*)(outHi + (size_t)r1 * DD + col) = h1;
                *(__nv_bfloat162*)(outLo + (size_t)r1 * DD + col) = l1;
                *(__nv_bfloat162*)(outHi + (size_t)r2 * DD + col) = h2;
                *(__nv_bfloat162*)(outLo + (size_t)r2 * DD + col) = l2;
            } else {
                *(__half2*)(outH + (size_t)r1 * DD + col) = __floats2half2_rn(v0, v1);
                *(__half2*)(outH + (size_t)r2 * DD + col) = __floats2half2_rn(v2, v3);
            }
        }
    }
}

// ---------------- causal flash attention, mma.sync + cp.async ----------------
// CTA = (qb, h, b): 128 q-rows x 64-key tiles, 256 threads (8 warps x 16 rows).
// Q in registers; K via ldmatrix, V via ldmatrix.trans. 3-stage KV ring,
// one sync per tile, warp-level skip of fully-masked diagonal tiles.
#define FLD 72
#define Q_BYTES (128*FLD*2)                   /* 18432 */
#define ST_ONE  (64*FLD*2)                    /* 9216  */
#define ST_BYTES (3*ST_ONE)                   /* 27648 */
#define FSTAGE 3
#define FLASH_SMEM (2*Q_BYTES + FSTAGE*ST_BYTES)  /* 119808 */

__global__ __launch_bounds__(256)
void flash_mma(const bf16* __restrict__ Qhi, const bf16* __restrict__ Qlo,
               const bf16* __restrict__ Khi, const bf16* __restrict__ Klo,
               const __half* __restrict__ Vh,
               bf16* __restrict__ Chi, bf16* __restrict__ Clo)
{
    extern __shared__ char smc[];
    const uint32_t smu = s2u(smc);
    const uint32_t qh_u = smu, ql_u = smu + Q_BYTES;
    const uint32_t st_u = smu + 2*Q_BYTES;

    const int t = threadIdx.x;
    const int w = t >> 5, lane = t & 31;
    const int g = lane >> 2, qd = lane & 3;
    const int qd2 = qd * 2;
    const int qb = (gridDim.x - 1) - blockIdx.x;   // heavy tiles first
    const int h = blockIdx.y, b = blockIdx.z;

    const size_t qrow0 = (size_t)b * SS + qb * 128;
    const size_t krow0 = (size_t)b * SS;
    const int hc = h * HDIM;
    const int kbmax = 2*qb + 1;

    const int qa_r = 16*w + (lane & 15);
    const int qa_c = (lane >> 4) * 8;
    const int kb_r = (lane & 7) + ((lane >> 4) << 3);
    const int kb_c = ((lane >> 3) & 1) * 8;
    const int v_r  = (lane & 7) + (((lane >> 3) & 1) << 3);
    const int v_c  = (lane >> 4) * 8;

    // ---- prologue: Q group, then KV tiles 0 and 1 ----
#pragma unroll
    for (int i = 0; i < 4; i++) {
        const int idx = t + 256*i;
        const int row = idx >> 3, col = (idx & 7) * 8;
        const uint32_t so = (uint32_t)(row*FLD + col) * 2;
        cpa16(qh_u + so, Qhi + (qrow0 + row)*DD + hc + col);
        cpa16(ql_u + so, Qlo + (qrow0 + row)*DD + hc + col);
    }
    cp_commit();

    auto issue_kv = [&](int kb) {
        const uint32_t sb = st_u + (kb % FSTAGE)*ST_BYTES;
#pragma unroll
        for (int i = 0; i < 2; i++) {
            const int idx = t + 256*i;
            const int row = idx >> 3, col = (idx & 7) * 8;
            const uint32_t so = (uint32_t)(row*FLD + col) * 2;
            const size_t gr = (krow0 + kb*64 + row)*DD + hc + col;
            cpa16(sb + so,            Khi + gr);
            cpa16(sb + ST_ONE + so,   Klo + gr);
            cpa16(sb + 2*ST_ONE + so, Vh  + gr);
        }
        cp_commit();
    };
    issue_kv(0);
    issue_kv(1);          // kbmax >= 1 always

    cp_wait<2>();         // Q arrived
    __syncthreads();

    uint32_t qa_h[4][4], qa_l[4][4];
#pragma unroll
    for (int s = 0; s < 4; s++) {
        ldsm4(qa_h[s], qh_u + (uint32_t)(qa_r*FLD + s*16 + qa_c)*2);
        ldsm4(qa_l[s], ql_u + (uint32_t)(qa_r*FLD + s*16 + qa_c)*2);
    }

    float sc[8][4], o[8][4];
#pragma unroll
    for (int j = 0; j < 8; j++)
#pragma unroll
        for (int e = 0; e < 4; e++) o[j][e] = 0.f;
    const float NEG_INF = __int_as_float(0xff800000u);
    float m0 = NEG_INF, m1 = NEG_INF, l0 = 0.f, l1 = 0.f;

    const int grow0 = qb*128 + 16*w + g;
    const int grow1 = grow0 + 8;
    const int wrow_max = qb*128 + 16*w + 15;  // last q row owned by this warp

    for (int kb = 0; kb <= kbmax; kb++) {
        const int st = kb % FSTAGE;
        if (kb == kbmax) cp_wait<0>();
        else             cp_wait<1>();
        __syncthreads();

        const bool active = (kb*64 <= wrow_max);   // else tile fully masked
        if (active) {
            const uint32_t skh = st_u + st*ST_BYTES;
            const uint32_t skl = skh + ST_ONE;
            const uint32_t svb = skh + 2*ST_ONE;

            // ---- scores (3-term split) ----
#pragma unroll
            for (int j = 0; j < 8; j++)
#pragma unroll
                for (int e = 0; e < 4; e++) sc[j][e] = 0.f;

#pragma unroll
            for (int s = 0; s < 4; s++) {
#pragma unroll
                for (int jp = 0; jp < 4; jp++) {
                    uint32_t bh[4], bl[4];
                    const uint32_t off =
                        (uint32_t)((jp*16 + kb_r)*FLD + s*16 + kb_c)*2;
                    ldsm4(bh, skh + off);
                    ldsm4(bl, skl + off);
                    mma_bf16(sc[2*jp  ], qa_h[s], bh);
                    mma_bf16(sc[2*jp+1], qa_h[s], bh + 2);
                    mma_bf16(sc[2*jp  ], qa_h[s], bl);
                    mma_bf16(sc[2*jp+1], qa_h[s], bl + 2);
                    mma_bf16(sc[2*jp  ], qa_l[s], bh);
                    mma_bf16(sc[2*jp+1], qa_l[s], bh + 2);
                }
            }

            // ---- scale + causal mask + online softmax ----
            const bool diag = (kb >= 2*qb);
            float mx0 = NEG_INF, mx1 = NEG_INF;
#pragma unroll
            for (int j = 0; j < 8; j++) {
                const int c0 = kb*64 + j*8 + qd2, c1 = c0 + 1;
                float s0 = sc[j][0]*0.125f, s1 = sc[j][1]*0.125f;
                float s2 = sc[j][2]*0.125f, s3 = sc[j][3]*0.125f;
                if (diag) {
                    if (c0 > grow0) s0 = NEG_INF;
                    if (c1 > grow0) s1 = NEG_INF;
                    if (c0 > grow1) s2 = NEG_INF;
                    if (c1 > grow1) s3 = NEG_INF;
                }
                sc[j][0] = s0; sc[j][1] = s1; sc[j][2] = s2; sc[j][3] = s3;
                mx0 = fmaxf(mx0, fmaxf(s0, s1));
                mx1 = fmaxf(mx1, fmaxf(s2, s3));
            }
            mx0 = fmaxf(mx0, __shfl_xor_sync(0xffffffffu, mx0, 1));
            mx0 = fmaxf(mx0, __shfl_xor_sync(0xffffffffu, mx0, 2));
            mx1 = fmaxf(mx1, __shfl_xor_sync(0xffffffffu, mx1, 1));
            mx1 = fmaxf(mx1, __shfl_xor_sync(0xffffffffu, mx1, 2));

            const float mn0 = fmaxf(m0, mx0), mn1 = fmaxf(m1, mx1);
            const float al0 = __expf(m0 - mn0), al1 = __expf(m1 - mn1);
            m0 = mn0; m1 = mn1;

            float s0sum = 0.f, s1sum = 0.f;
#pragma unroll
            for (int j = 0; j < 8; j++) {
                const float p0 = __expf(sc[j][0] - mn0);
                const float p1 = __expf(sc[j][1] - mn0);
                const float p2 = __expf(sc[j][2] - mn1);
                const float p3 = __expf(sc[j][3] - mn1);
                sc[j][0] = p0; sc[j][1] = p1; sc[j][2] = p2; sc[j][3] = p3;
                s0sum += p0 + p1; s1sum += p2 + p3;
            }
            s0sum += __shfl_xor_sync(0xffffffffu, s0sum, 1);
            s0sum += __shfl_xor_sync(0xffffffffu, s0sum, 2);
            s1sum += __shfl_xor_sync(0xffffffffu, s1sum, 1);
            s1sum += __shfl_xor_sync(0xffffffffu, s1sum, 2);
            l0 = l0 * al0 + s0sum;
            l1 = l1 * al1 + s1sum;

#pragma unroll
            for (int j = 0; j < 8; j++) {
                o[j][0] *= al0; o[j][1] *= al0;
                o[j][2] *= al1; o[j][3] *= al1;
            }

            // ---- o += P @ V  (fp16, V via ldmatrix.trans) ----
#pragma unroll
            for (int s = 0; s < 4; s++) {
                uint32_t a[4];
                a[0] = h2_as_u32(__floats2half2_rn(sc[2*s  ][0], sc[2*s  ][1]));
                a[1] = h2_as_u32(__floats2half2_rn(sc[2*s  ][2], sc[2*s  ][3]));
                a[2] = h2_as_u32(__floats2half2_rn(sc[2*s+1][0], sc[2*s+1][1]));
                a[3] = h2_as_u32(__floats2half2_rn(sc[2*s+1][2], sc[2*s+1][3]));
#pragma unroll
                for (int jp = 0; jp < 4; jp++) {
                    uint32_t bv[4];
                    ldsm4t(bv, svb + (uint32_t)((s*16 + v_r)*FLD + jp*16 + v_c)*2);
                    mma_f16(o[2*jp  ], a, bv);
                    mma_f16(o[2*jp+1], a, bv + 2);
                }
            }
        }
        if (kb + 2 <= kbmax) issue_kv(kb + 2);  // writes stage (kb-1)%3: retired
    }

    // ---- epilogue: normalize, split to bf16 hi/lo ----
    const float inv0 = 1.f / l0, inv1 = 1.f / l1;
    const size_t r1 = qrow0 + 16*w + g;
    const size_t r2 = r1 + 8;
#pragma unroll
    for (int j = 0; j < 8; j++) {
        const int col = hc + j*8 + qd2;
        const float v0 = o[j][0]*inv0, v1 = o[j][1]*inv0;
        const float v2 = o[j][2]*inv1, v3 = o[j][3]*inv1;
        __nv_bfloat162 h1, lo1, h2, lo2;
        h1.x = __float2bfloat16(v0); h1.y = __float2bfloat16(v1);
        lo1.x = __float2bfloat16(v0 - __bfloat162float(h1.x));
        lo1.y = __float2bfloat16(v1 - __bfloat162float(h1.y));
        h2.x = __float2bfloat16(v2); h2.y = __float2bfloat16(v3);
        lo2.x = __float2bfloat16(v2 - __bfloat162float(h2.x));
        lo2.y = __float2bfloat16(v3 - __bfloat162float(h2.y));
        *(__nv_bfloat162*)(Chi + r1*DD + col) = h1;
        *(__nv_bfloat162*)(Clo + r1*DD + col) = lo1;
        *(__nv_bfloat162*)(Chi + r2*DD + col) = h2;
        *(__nv_bfloat162*)(Clo + r2*DD + col) = lo2;
    }
}

// ---------------------------------------------------------------------------
extern "C" void kernel_launch(void* const* d_in, const int* in_sizes, int n_in,
                              void* d_out, int out_size)
{
    const float* x  = (const float*)d_in[0];
    const float* Wq = (const float*)d_in[1];
    const float* Wk = (const float*)d_in[2];
    const float* Wv = (const float*)d_in[3];
    const float* Wo = (const float*)d_in[4];
    const float* bo = (const float*)d_in[5];
    float* out = (float*)d_out;

    bf16 *xhi, *xlo, *qhi, *qlo, *khi, *klo, *chi, *clo, *wt;
    __half* vh;
    cudaGetSymbolAddress((void**)&xhi, g_xhi);
    cudaGetSymbolAddress((void**)&xlo, g_xlo);
    cudaGetSymbolAddress((void**)&qhi, g_qhi);
    cudaGetSymbolAddress((void**)&qlo, g_qlo);
    cudaGetSymbolAddress((void**)&khi, g_khi);
    cudaGetSymbolAddress((void**)&klo, g_klo);
    cudaGetSymbolAddress((void**)&vh,  g_vh);
    cudaGetSymbolAddress((void**)&chi, g_chi);
    cudaGetSymbolAddress((void**)&clo, g_clo);
    cudaGetSymbolAddress((void**)&wt,  g_wt);
    bf16* w[8];
    for (int i = 0; i < 8; i++) w[i] = wt + (size_t)i * DD * DD;

    cudaFuncSetAttribute(gemm_mma<0>,
                         cudaFuncAttributeMaxDynamicSharedMemorySize, GEMM_SMEM);
    cudaFuncSetAttribute(gemm_mma<1>,
                         cudaFuncAttributeMaxDynamicSharedMemorySize, GEMM_SMEM);
    cudaFuncSetAttribute(gemm_mma<2>,
                         cudaFuncAttributeMaxDynamicSharedMemorySize, GEMM_SMEM);
    cudaFuncSetAttribute(flash_mma,
                         cudaFuncAttributeMaxDynamicSharedMemorySize, FLASH_SMEM);

    // weight transpose + split (one launch)
    dim3 wb(32, 8), wg(DD/32, DD/32, 4);
    wsplit4_kernel<<<wg, wb>>>(Wq, Wk, Wv, Wo, wt);

    // x split
    const int n4 = MROWS * DD / 4;
    fsplit_kernel<<<n4 / 256, 256>>>((const float4*)x,
                                     (__nv_bfloat162*)xhi, (__nv_bfloat162*)xlo, n4);

    // projections
    dim3 gg(DD / 128, MROWS / 128);   // (8, 64)
    gemm_mma<1><<<gg, 256, GEMM_SMEM>>>(xhi, xlo, w[0], w[1], nullptr,
                                        nullptr, qhi, qlo, nullptr);
    gemm_mma<1><<<gg, 256, GEMM_SMEM>>>(xhi, xlo, w[2], w[3], nullptr,
                                        nullptr, khi, klo, nullptr);
    gemm_mma<2><<<gg, 256, GEMM_SMEM>>>(xhi, xlo, w[4], w[5], nullptr,
                                        nullptr, nullptr, nullptr, vh);

    // attention
    dim3 gf(SS / 128, NH, BB);        // (16, 16, 4)
    flash_mma<<<gf, 256, FLASH_SMEM>>>(qhi, qlo, khi, klo, vh, chi, clo);

    // output projection + bias
    gemm_mma<0><<<gg, 256, GEMM_SMEM>>>(chi, clo, w[6], w[7], bo,
                                        out, nullptr, nullptr, nullptr);
}

// round 7
// speedup vs baseline: 4.8248x; 1.1939x over previous
#include <cuda_runtime.h>
#include <cuda_bf16.h>
#include <cuda_fp16.h>
#include <math.h>
#include <stdint.h>

#define BB 4
#define SS 2048
#define DD 1024
#define NH 16
#define HDIM 64
#define MROWS (BB*SS)   /* 8192 */

typedef __nv_bfloat16 bf16;

// ---------------- scratch (__device__ globals; allocs forbidden) ------------
__device__ bf16  g_xhi[MROWS*DD];
__device__ bf16  g_xlo[MROWS*DD];
__device__ bf16  g_qhi[MROWS*DD];
__device__ bf16  g_qlo[MROWS*DD];
__device__ bf16  g_khi[MROWS*DD];
__device__ bf16  g_klo[MROWS*DD];
__device__ __half g_vh[MROWS*DD];
__device__ bf16  g_chi[MROWS*DD];
__device__ bf16  g_clo[MROWS*DD];
__device__ bf16  g_wt[8][DD*DD];   // [Wq_hi,Wq_lo,Wk_hi,Wk_lo,Wv_hi,Wv_lo,Wo_hi,Wo_lo]

// ---------------- ptx helpers -------------------------------------------------
static __device__ __forceinline__ void mma_bf16(float* c, const uint32_t* a,
                                                const uint32_t* b) {
    asm volatile(
        "mma.sync.aligned.m16n8k16.row.col.f32.bf16.bf16.f32 "
        "{%0,%1,%2,%3}, {%4,%5,%6,%7}, {%8,%9}, {%0,%1,%2,%3};"
        : "+f"(c[0]), "+f"(c[1]), "+f"(c[2]), "+f"(c[3])
        : "r"(a[0]), "r"(a[1]), "r"(a[2]), "r"(a[3]), "r"(b[0]), "r"(b[1]));
}
static __device__ __forceinline__ void mma_f16(float* c, const uint32_t* a,
                                               const uint32_t* b) {
    asm volatile(
        "mma.sync.aligned.m16n8k16.row.col.f32.f16.f16.f32 "
        "{%0,%1,%2,%3}, {%4,%5,%6,%7}, {%8,%9}, {%0,%1,%2,%3};"
        : "+f"(c[0]), "+f"(c[1]), "+f"(c[2]), "+f"(c[3])
        : "r"(a[0]), "r"(a[1]), "r"(a[2]), "r"(a[3]), "r"(b[0]), "r"(b[1]));
}
static __device__ __forceinline__ void ldsm4(uint32_t* r, uint32_t a) {
    asm volatile("ldmatrix.sync.aligned.m8n8.x4.shared.b16 {%0,%1,%2,%3}, [%4];"
                 : "=r"(r[0]), "=r"(r[1]), "=r"(r[2]), "=r"(r[3]) : "r"(a));
}
static __device__ __forceinline__ void ldsm4t(uint32_t* r, uint32_t a) {
    asm volatile("ldmatrix.sync.aligned.m8n8.x4.trans.shared.b16 {%0,%1,%2,%3}, [%4];"
                 : "=r"(r[0]), "=r"(r[1]), "=r"(r[2]), "=r"(r[3]) : "r"(a));
}
static __device__ __forceinline__ uint32_t s2u(const void* p) {
    uint32_t a;
    asm("{ .reg .u64 t; cvta.to.shared.u64 t, %1; cvt.u32.u64 %0, t; }"
        : "=r"(a) : "l"(p));
    return a;
}
static __device__ __forceinline__ void cpa16(uint32_t dst, const void* src) {
    asm volatile("cp.async.cg.shared.global [%0], [%1], 16;"
                 :: "r"(dst), "l"(src));
}
static __device__ __forceinline__ void cp_commit() {
    asm volatile("cp.async.commit_group;");
}
template<int N>
static __device__ __forceinline__ void cp_wait() {
    asm volatile("cp.async.wait_group %0;" :: "n"(N));
}
static __device__ __forceinline__ uint32_t h2_as_u32(__half2 v) {
    union { __half2 h; uint32_t u; } cvt;
    cvt.h = v;
    return cvt.u;
}

// ---------------- split / transpose kernels ---------------------------------
__global__ void fsplit_kernel(const float4* __restrict__ x,
                              __nv_bfloat162* __restrict__ hi,
                              __nv_bfloat162* __restrict__ lo, int n4)
{
    int i = blockIdx.x * blockDim.x + threadIdx.x;
    if (i >= n4) return;
    float4 v = x[i];
    bf16 h0 = __float2bfloat16(v.x), h1 = __float2bfloat16(v.y);
    bf16 h2 = __float2bfloat16(v.z), h3 = __float2bfloat16(v.w);
    __nv_bfloat162 a, b, c, d;
    a.x = h0; a.y = h1; b.x = h2; b.y = h3;
    c.x = __float2bfloat16(v.x - __bfloat162float(h0));
    c.y = __float2bfloat16(v.y - __bfloat162float(h1));
    d.x = __float2bfloat16(v.z - __bfloat162float(h2));
    d.y = __float2bfloat16(v.w - __bfloat162float(h3));
    hi[2*i] = a; hi[2*i+1] = b;
    lo[2*i] = c; lo[2*i+1] = d;
}

__global__ void wsplit4_kernel(const float* __restrict__ W0,
                               const float* __restrict__ W1,
                               const float* __restrict__ W2,
                               const float* __restrict__ W3,
                               bf16* __restrict__ wt)
{
    __shared__ float t[32][33];
    const float* Ws[4] = {W0, W1, W2, W3};
    const int z = blockIdx.z;
    const float* W = Ws[z];
    bf16* thi = wt + (size_t)(2*z)   * DD * DD;
    bf16* tlo = wt + (size_t)(2*z+1) * DD * DD;

    const int n0 = blockIdx.x * 32, k0 = blockIdx.y * 32;
    const int tx = threadIdx.x, ty = threadIdx.y;
#pragma unroll
    for (int i = 0; i < 32; i += 8)
        t[ty + i][tx] = W[(size_t)(k0 + ty + i) * DD + n0 + tx];
    __syncthreads();
#pragma unroll
    for (int i = 0; i < 32; i += 8) {
        float v = t[tx][ty + i];
        bf16 h = __float2bfloat16(v);
        float r = v - __bfloat162float(h);
        size_t o = (size_t)(n0 + ty + i) * DD + k0 + tx;
        thi[o] = h;
        tlo[o] = __float2bfloat16(r);
    }
}

// ---------------- fused mma.sync bf16 split GEMM ------------------------------
// One kernel for all projections. sel = sel_base + blockIdx.x/8:
//   0: x@Wq -> qhi/qlo   1: x@Wk -> khi/klo   2: x@Wv -> vh   3: ctx@Wo+bias -> outF
// CTA 128x128, BK=64 stages, 3-stage cp.async ring, 1 barrier per stage.
#define ALD2 72
#define G_MAT2 (128*ALD2)                       /* elems per matrix stage */
#define NSTG 48                                 /* 3 terms x 16 stages of K=64 */
#define GEMM_SMEM (2 * 3 * G_MAT2 * 2)          /* 110592 bytes */

__global__ __launch_bounds__(256, 2)
void gemm_fused(const bf16* __restrict__ Ahi, const bf16* __restrict__ Alo,
                const bf16* __restrict__ wt, const float* __restrict__ bias,
                bf16* __restrict__ qhi, bf16* __restrict__ qlo,
                bf16* __restrict__ khi, bf16* __restrict__ klo,
                __half* __restrict__ vh, float* __restrict__ outF,
                int sel_base)
{
    extern __shared__ char smg[];
    const uint32_t asu = s2u(smg);
    const uint32_t bsu = asu + 3 * G_MAT2 * 2;

    const int t = threadIdx.x;
    const int wid = t >> 5, lane = t & 31;
    const int wm = wid & 1, wn = wid >> 1;
    const int g = lane >> 2, qd = lane & 3;
    const int qd2 = qd * 2;
    const int sel = sel_base + (blockIdx.x >> 3);
    const int n0 = (blockIdx.x & 7) * 128;
    const int m0 = blockIdx.y * 128;

    const bf16* Bhi = wt + (size_t)(2*sel)   * DD * DD;
    const bf16* Blo = wt + (size_t)(2*sel+1) * DD * DD;
    const bf16* Aterm[3] = {Ahi, Ahi, Alo};
    const bf16* Bterm[3] = {Bhi, Blo, Bhi};

    const int ld_row = t >> 3;            // 0..31 (+32 per sweep, 4 sweeps)
    const int ld_col = (t & 7) * 8;       // elems (16B units)

    const int a_r = wm*64 + (lane & 15);
    const int a_c = (lane >> 4) * 8;
    const int b_r = wn*32 + (lane & 7) + ((lane >> 4) << 3);
    const int b_c = ((lane >> 3) & 1) * 8;

    float acc[4][4][4];
#pragma unroll
    for (int i = 0; i < 4; i++)
#pragma unroll
        for (int j = 0; j < 4; j++)
#pragma unroll
            for (int e = 0; e < 4; e++) acc[i][j][e] = 0.f;

    auto issue = [&](int s) {
        const int st = s % 3;
        const int term = s >> 4;
        const int kc = (s & 15) * 64;
        const bf16* A = Aterm[term];
        const bf16* B = Bterm[term];
#pragma unroll
        for (int i = 0; i < 4; i++) {
            const int row = ld_row + i*32;
            const uint32_t so = (uint32_t)(st*G_MAT2 + row*ALD2 + ld_col) * 2;
            cpa16(asu + so, A + (size_t)(m0 + row) * DD + kc + ld_col);
            cpa16(bsu + so, B + (size_t)(n0 + row) * DD + kc + ld_col);
        }
        cp_commit();
    };

    issue(0);
    issue(1);

    for (int s = 0; s < NSTG; s++) {
        const int st = s % 3;
        if (s == NSTG - 1) cp_wait<0>();
        else               cp_wait<1>();
        __syncthreads();

        const uint32_t ab = asu + (uint32_t)(st*G_MAT2)*2;
        const uint32_t bb = bsu + (uint32_t)(st*G_MAT2)*2;
#pragma unroll
        for (int kk = 0; kk < 4; kk++) {
            uint32_t a[4][4], b4[2][4];
#pragma unroll
            for (int i = 0; i < 4; i++)
                ldsm4(a[i], ab + (uint32_t)((a_r + i*16)*ALD2 + kk*16 + a_c)*2);
#pragma unroll
            for (int jp = 0; jp < 2; jp++)
                ldsm4(b4[jp], bb + (uint32_t)((b_r + jp*16)*ALD2 + kk*16 + b_c)*2);
#pragma unroll
            for (int i = 0; i < 4; i++)
#pragma unroll
                for (int j = 0; j < 4; j++)
                    mma_bf16(acc[i][j], a[i], &b4[j >> 1][(j & 1) * 2]);
        }
        if (s + 2 < NSTG) issue(s + 2);   // writes stage (s-1)%3: retired by barrier
    }

    // epilogue
    bf16* oHi = (sel == 0) ? qhi : khi;
    bf16* oLo = (sel == 0) ? qlo : klo;
#pragma unroll
    for (int i = 0; i < 4; i++) {
        const int r1 = m0 + wm*64 + i*16 + g;
        const int r2 = r1 + 8;
#pragma unroll
        for (int j = 0; j < 4; j++) {
            const int col = n0 + wn*32 + j*8 + qd2;
            const float v0 = acc[i][j][0], v1 = acc[i][j][1];
            const float v2 = acc[i][j][2], v3 = acc[i][j][3];
            if (sel == 3) {
                float2 o1, o2;
                o1.x = v0 + bias[col]; o1.y = v1 + bias[col+1];
                o2.x = v2 + bias[col]; o2.y = v3 + bias[col+1];
                *(float2*)(outF + (size_t)r1 * DD + col) = o1;
                *(float2*)(outF + (size_t)r2 * DD + col) = o2;
            } else if (sel == 2) {
                *(__half2*)(vh + (size_t)r1 * DD + col) = __floats2half2_rn(v0, v1);
                *(__half2*)(vh + (size_t)r2 * DD + col) = __floats2half2_rn(v2, v3);
            } else {
                __nv_bfloat162 h1, l1, h2, l2;
                h1.x = __float2bfloat16(v0); h1.y = __float2bfloat16(v1);
                l1.x = __float2bfloat16(v0 - __bfloat162float(h1.x));
                l1.y = __float2bfloat16(v1 - __bfloat162float(h1.y));
                h2.x = __float2bfloat16(v2); h2.y = __float2bfloat16(v3);
                l2.x = __float2bfloat16(v2 - __bfloat162float(h2.x));
                l2.y = __float2bfloat16(v3 - __bfloat162float(h2.y));
                *(__nv_bfloat162*)(oHi + (size_t)r1 * DD + col) = h1;
                *(__nv_bfloat162*)(oLo + (size_t)r1 * DD + col) = l1;
                *(__nv_bfloat162*)(oHi + (size_t)r2 * DD + col) = h2;
                *(__nv_bfloat162*)(oLo + (size_t)r2 * DD + col) = l2;
            }
        }
    }
}

// ---------------- causal flash attention, mma.sync + cp.async ----------------
// 128 q-rows x 64-key tiles, 256 threads. Q staged through the KV ring region
// (register-resident afterwards) so smem = 3 KV stages -> 2 CTAs/SM.
#define FLD 72
#define ST_ONE  (64*FLD*2)                    /* 9216  */
#define ST_BYTES (3*ST_ONE)                   /* 27648 */
#define Q_BYTES (128*FLD*2)                   /* 18432 */
#define FLASH_SMEM (3*ST_BYTES)               /* 82944 >= 2*Q_BYTES */

__global__ __launch_bounds__(256, 2)
void flash_mma(const bf16* __restrict__ Qhi, const bf16* __restrict__ Qlo,
               const bf16* __restrict__ Khi, const bf16* __restrict__ Klo,
               const __half* __restrict__ Vh,
               bf16* __restrict__ Chi, bf16* __restrict__ Clo)
{
    extern __shared__ char smc[];
    const uint32_t smu = s2u(smc);

    const int t = threadIdx.x;
    const int w = t >> 5, lane = t & 31;
    const int g = lane >> 2, qd = lane & 3;
    const int qd2 = qd * 2;
    const int qb = (gridDim.x - 1) - blockIdx.x;   // heavy tiles first
    const int h = blockIdx.y, b = blockIdx.z;

    const size_t qrow0 = (size_t)b * SS + qb * 128;
    const size_t krow0 = (size_t)b * SS;
    const int hc = h * HDIM;
    const int kbmax = 2*qb + 1;

    const int qa_r = 16*w + (lane & 15);
    const int qa_c = (lane >> 4) * 8;
    const int kb_r = (lane & 7) + ((lane >> 4) << 3);
    const int kb_c = ((lane >> 3) & 1) * 8;
    const int v_r  = (lane & 7) + (((lane >> 3) & 1) << 3);
    const int v_c  = (lane >> 4) * 8;

    // ---- Q staging through smem (region reused by KV ring afterwards) ----
#pragma unroll
    for (int i = 0; i < 4; i++) {
        const int idx = t + 256*i;
        const int row = idx >> 3, col = (idx & 7) * 8;
        const uint32_t so = (uint32_t)(row*FLD + col) * 2;
        cpa16(smu + so,           Qhi + (qrow0 + row)*DD + hc + col);
        cpa16(smu + Q_BYTES + so, Qlo + (qrow0 + row)*DD + hc + col);
    }
    cp_commit();
    cp_wait<0>();
    __syncthreads();

    uint32_t qa_h[4][4], qa_l[4][4];
#pragma unroll
    for (int s = 0; s < 4; s++) {
        ldsm4(qa_h[s], smu + (uint32_t)(qa_r*FLD + s*16 + qa_c)*2);
        ldsm4(qa_l[s], smu + Q_BYTES + (uint32_t)(qa_r*FLD + s*16 + qa_c)*2);
    }
    __syncthreads();                    // all warps done reading Q region

    auto issue_kv = [&](int kb) {
        const uint32_t sb = smu + (kb % 3)*ST_BYTES;
#pragma unroll
        for (int i = 0; i < 2; i++) {
            const int idx = t + 256*i;
            const int row = idx >> 3, col = (idx & 7) * 8;
            const uint32_t so = (uint32_t)(row*FLD + col) * 2;
            const size_t gr = (krow0 + kb*64 + row)*DD + hc + col;
            cpa16(sb + so,            Khi + gr);
            cpa16(sb + ST_ONE + so,   Klo + gr);
            cpa16(sb + 2*ST_ONE + so, Vh  + gr);
        }
        cp_commit();
    };
    issue_kv(0);
    issue_kv(1);                        // kbmax >= 1 always

    float sc[8][4], o[8][4];
#pragma unroll
    for (int j = 0; j < 8; j++)
#pragma unroll
        for (int e = 0; e < 4; e++) o[j][e] = 0.f;
    const float NEG_INF = __int_as_float(0xff800000u);
    float m0 = NEG_INF, m1 = NEG_INF, l0 = 0.f, l1 = 0.f;

    const int grow0 = qb*128 + 16*w + g;
    const int grow1 = grow0 + 8;
    const int wrow_max = qb*128 + 16*w + 15;

    for (int kb = 0; kb <= kbmax; kb++) {
        const int st = kb % 3;
        if (kb == kbmax) cp_wait<0>();
        else             cp_wait<1>();
        __syncthreads();

        const bool active = (kb*64 <= wrow_max);
        if (active) {
            const uint32_t skh = smu + st*ST_BYTES;
            const uint32_t skl = skh + ST_ONE;
            const uint32_t svb = skh + 2*ST_ONE;

#pragma unroll
            for (int j = 0; j < 8; j++)
#pragma unroll
                for (int e = 0; e < 4; e++) sc[j][e] = 0.f;

#pragma unroll
            for (int s = 0; s < 4; s++) {
#pragma unroll
                for (int jp = 0; jp < 4; jp++) {
                    uint32_t bh[4], bl[4];
                    const uint32_t off =
                        (uint32_t)((jp*16 + kb_r)*FLD + s*16 + kb_c)*2;
                    ldsm4(bh, skh + off);
                    ldsm4(bl, skl + off);
                    mma_bf16(sc[2*jp  ], qa_h[s], bh);
                    mma_bf16(sc[2*jp+1], qa_h[s], bh + 2);
                    mma_bf16(sc[2*jp  ], qa_h[s], bl);
                    mma_bf16(sc[2*jp+1], qa_h[s], bl + 2);
                    mma_bf16(sc[2*jp  ], qa_l[s], bh);
                    mma_bf16(sc[2*jp+1], qa_l[s], bh + 2);
                }
            }

            const bool diag = (kb >= 2*qb);
            float mx0 = NEG_INF, mx1 = NEG_INF;
#pragma unroll
            for (int j = 0; j < 8; j++) {
                const int c0 = kb*64 + j*8 + qd2, c1 = c0 + 1;
                float s0 = sc[j][0]*0.125f, s1 = sc[j][1]*0.125f;
                float s2 = sc[j][2]*0.125f, s3 = sc[j][3]*0.125f;
                if (diag) {
                    if (c0 > grow0) s0 = NEG_INF;
                    if (c1 > grow0) s1 = NEG_INF;
                    if (c0 > grow1) s2 = NEG_INF;
                    if (c1 > grow1) s3 = NEG_INF;
                }
                sc[j][0] = s0; sc[j][1] = s1; sc[j][2] = s2; sc[j][3] = s3;
                mx0 = fmaxf(mx0, fmaxf(s0, s1));
                mx1 = fmaxf(mx1, fmaxf(s2, s3));
            }
            mx0 = fmaxf(mx0, __shfl_xor_sync(0xffffffffu, mx0, 1));
            mx0 = fmaxf(mx0, __shfl_xor_sync(0xffffffffu, mx0, 2));
            mx1 = fmaxf(mx1, __shfl_xor_sync(0xffffffffu, mx1, 1));
            mx1 = fmaxf(mx1, __shfl_xor_sync(0xffffffffu, mx1, 2));

            const float mn0 = fmaxf(m0, mx0), mn1 = fmaxf(m1, mx1);
            const float al0 = __expf(m0 - mn0), al1 = __expf(m1 - mn1);
            m0 = mn0; m1 = mn1;

            float s0sum = 0.f, s1sum = 0.f;
#pragma unroll
            for (int j = 0; j < 8; j++) {
                const float p0 = __expf(sc[j][0] - mn0);
                const float p1 = __expf(sc[j][1] - mn0);
                const float p2 = __expf(sc[j][2] - mn1);
                const float p3 = __expf(sc[j][3] - mn1);
                sc[j][0] = p0; sc[j][1] = p1; sc[j][2] = p2; sc[j][3] = p3;
                s0sum += p0 + p1; s1sum += p2 + p3;
            }
            s0sum += __shfl_xor_sync(0xffffffffu, s0sum, 1);
            s0sum += __shfl_xor_sync(0xffffffffu, s0sum, 2);
            s1sum += __shfl_xor_sync(0xffffffffu, s1sum, 1);
            s1sum += __shfl_xor_sync(0xffffffffu, s1sum, 2);
            l0 = l0 * al0 + s0sum;
            l1 = l1 * al1 + s1sum;

#pragma unroll
            for (int j = 0; j < 8; j++) {
                o[j][0] *= al0; o[j][1] *= al0;
                o[j][2] *= al1; o[j][3] *= al1;
            }

#pragma unroll
            for (int s = 0; s < 4; s++) {
                uint32_t a[4];
                a[0] = h2_as_u32(__floats2half2_rn(sc[2*s  ][0], sc[2*s  ][1]));
                a[1] = h2_as_u32(__floats2half2_rn(sc[2*s  ][2], sc[2*s  ][3]));
                a[2] = h2_as_u32(__floats2half2_rn(sc[2*s+1][0], sc[2*s+1][1]));
                a[3] = h2_as_u32(__floats2half2_rn(sc[2*s+1][2], sc[2*s+1][3]));
#pragma unroll
                for (int jp = 0; jp < 4; jp++) {
                    uint32_t bv[4];
                    ldsm4t(bv, svb + (uint32_t)((s*16 + v_r)*FLD + jp*16 + v_c)*2);
                    mma_f16(o[2*jp  ], a, bv);
                    mma_f16(o[2*jp+1], a, bv + 2);
                }
            }
        }
        if (kb + 2 <= kbmax) issue_kv(kb + 2);
    }

    // ---- epilogue ----
    const float inv0 = 1.f / l0, inv1 = 1.f / l1;
    const size_t r1 = qrow0 + 16*w + g;
    const size_t r2 = r1 + 8;
#pragma unroll
    for (int j = 0; j < 8; j++) {
        const int col = hc + j*8 + qd2;
        const float v0 = o[j][0]*inv0, v1 = o[j][1]*inv0;
        const float v2 = o[j][2]*inv1, v3 = o[j][3]*inv1;
        __nv_bfloat162 h1, lo1, h2, lo2;
        h1.x = __float2bfloat16(v0); h1.y = __float2bfloat16(v1);
        lo1.x = __float2bfloat16(v0 - __bfloat162float(h1.x));
        lo1.y = __float2bfloat16(v1 - __bfloat162float(h1.y));
        h2.x = __float2bfloat16(v2); h2.y = __float2bfloat16(v3);
        lo2.x = __float2bfloat16(v2 - __bfloat162float(h2.x));
        lo2.y = __float2bfloat16(v3 - __bfloat162float(h2.y));
        *(__nv_bfloat162*)(Chi + r1*DD + col) = h1;
        *(__nv_bfloat162*)(Clo + r1*DD + col) = lo1;
        *(__nv_bfloat162*)(Chi + r2*DD + col) = h2;
        *(__nv_bfloat162*)(Clo + r2*DD + col) = lo2;
    }
}

// ---------------------------------------------------------------------------
extern "C" void kernel_launch(void* const* d_in, const int* in_sizes, int n_in,
                              void* d_out, int out_size)
{
    const float* x  = (const float*)d_in[0];
    const float* Wq = (const float*)d_in[1];
    const float* Wk = (const float*)d_in[2];
    const float* Wv = (const float*)d_in[3];
    const float* Wo = (const float*)d_in[4];
    const float* bo = (const float*)d_in[5];
    float* out = (float*)d_out;

    bf16 *xhi, *xlo, *qhi, *qlo, *khi, *klo, *chi, *clo, *wt;
    __half* vh;
    cudaGetSymbolAddress((void**)&xhi, g_xhi);
    cudaGetSymbolAddress((void**)&xlo, g_xlo);
    cudaGetSymbolAddress((void**)&qhi, g_qhi);
    cudaGetSymbolAddress((void**)&qlo, g_qlo);
    cudaGetSymbolAddress((void**)&khi, g_khi);
    cudaGetSymbolAddress((void**)&klo, g_klo);
    cudaGetSymbolAddress((void**)&vh,  g_vh);
    cudaGetSymbolAddress((void**)&chi, g_chi);
    cudaGetSymbolAddress((void**)&clo, g_clo);
    cudaGetSymbolAddress((void**)&wt,  g_wt);

    cudaFuncSetAttribute(gemm_fused,
                         cudaFuncAttributeMaxDynamicSharedMemorySize, GEMM_SMEM);
    cudaFuncSetAttribute(flash_mma,
                         cudaFuncAttributeMaxDynamicSharedMemorySize, FLASH_SMEM);

    // weight transpose + split
    dim3 wb(32, 8), wg(DD/32, DD/32, 4);
    wsplit4_kernel<<<wg, wb>>>(Wq, Wk, Wv, Wo, wt);

    // x split
    const int n4 = MROWS * DD / 4;
    fsplit_kernel<<<n4 / 256, 256>>>((const float4*)x,
                                     (__nv_bfloat162*)xhi, (__nv_bfloat162*)xlo, n4);

    // fused QKV projections (one launch)
    dim3 gq(3 * DD / 128, MROWS / 128);   // (24, 64)
    gemm_fused<<<gq, 256, GEMM_SMEM>>>(xhi, xlo, wt, nullptr,
                                       qhi, qlo, khi, klo, vh, nullptr, 0);

    // attention
    dim3 gf(SS / 128, NH, BB);            // (16, 16, 4)
    flash_mma<<<gf, 256, FLASH_SMEM>>>(qhi, qlo, khi, klo, vh, chi, clo);

    // output projection + bias
    dim3 go(DD / 128, MROWS / 128);       // (8, 64)
    gemm_fused<<<go, 256, GEMM_SMEM>>>(chi, clo, wt, bo,
                                       nullptr, nullptr, nullptr, nullptr,
                                       nullptr, out, 3);
}

// round 8
// speedup vs baseline: 8.4491x; 1.7512x over previous
#include <cuda_runtime.h>
#include <cuda_bf16.h>
#include <cuda_fp16.h>
#include <math.h>
#include <stdint.h>

#define BB 4
#define SS 2048
#define DD 1024
#define NH 16
#define HDIM 64
#define MROWS (BB*SS)   /* 8192 */

// ---------------- scratch (__device__ globals; allocs forbidden) ------------
__device__ __half g_xh[MROWS*DD];
__device__ __half g_qh[MROWS*DD];
__device__ __half g_ql[MROWS*DD];
__device__ __half g_kh[MROWS*DD];
__device__ __half g_kl[MROWS*DD];
__device__ __half g_vh[MROWS*DD];
__device__ __half g_ch[MROWS*DD];
__device__ __half g_wh[4][DD*DD];   // transposed fp16: [Wq, Wk, Wv, Wo]

// ---------------- ptx helpers -------------------------------------------------
static __device__ __forceinline__ void mma_f16(float* c, const uint32_t* a,
                                               const uint32_t* b) {
    asm volatile(
        "mma.sync.aligned.m16n8k16.row.col.f32.f16.f16.f32 "
        "{%0,%1,%2,%3}, {%4,%5,%6,%7}, {%8,%9}, {%0,%1,%2,%3};"
        : "+f"(c[0]), "+f"(c[1]), "+f"(c[2]), "+f"(c[3])
        : "r"(a[0]), "r"(a[1]), "r"(a[2]), "r"(a[3]), "r"(b[0]), "r"(b[1]));
}
static __device__ __forceinline__ void ldsm4(uint32_t* r, uint32_t a) {
    asm volatile("ldmatrix.sync.aligned.m8n8.x4.shared.b16 {%0,%1,%2,%3}, [%4];"
                 : "=r"(r[0]), "=r"(r[1]), "=r"(r[2]), "=r"(r[3]) : "r"(a));
}
static __device__ __forceinline__ void ldsm4t(uint32_t* r, uint32_t a) {
    asm volatile("ldmatrix.sync.aligned.m8n8.x4.trans.shared.b16 {%0,%1,%2,%3}, [%4];"
                 : "=r"(r[0]), "=r"(r[1]), "=r"(r[2]), "=r"(r[3]) : "r"(a));
}
static __device__ __forceinline__ uint32_t s2u(const void* p) {
    uint32_t a;
    asm("{ .reg .u64 t; cvta.to.shared.u64 t, %1; cvt.u32.u64 %0, t; }"
        : "=r"(a) : "l"(p));
    return a;
}
static __device__ __forceinline__ void cpa16(uint32_t dst, const void* src) {
    asm volatile("cp.async.cg.shared.global [%0], [%1], 16;"
                 :: "r"(dst), "l"(src));
}
static __device__ __forceinline__ void cp_commit() {
    asm volatile("cp.async.commit_group;");
}
template<int N>
static __device__ __forceinline__ void cp_wait() {
    asm volatile("cp.async.wait_group %0;" :: "n"(N));
}
static __device__ __forceinline__ uint32_t h2_as_u32(__half2 v) {
    union { __half2 h; uint32_t u; } cvt;
    cvt.h = v;
    return cvt.u;
}

// ---------------- convert / transpose kernels --------------------------------
__global__ void xhalf_kernel(const float4* __restrict__ x,
                             __half2* __restrict__ xh, int n4)
{
    int i = blockIdx.x * blockDim.x + threadIdx.x;
    if (i >= n4) return;
    float4 v = x[i];
    xh[2*i]   = __floats2half2_rn(v.x, v.y);
    xh[2*i+1] = __floats2half2_rn(v.z, v.w);
}

__global__ void wtrans4_kernel(const float* __restrict__ W0,
                               const float* __restrict__ W1,
                               const float* __restrict__ W2,
                               const float* __restrict__ W3,
                               __half* __restrict__ wh)
{
    __shared__ float t[32][33];
    const float* Ws[4] = {W0, W1, W2, W3};
    const int z = blockIdx.z;
    const float* W = Ws[z];
    __half* th = wh + (size_t)z * DD * DD;

    const int n0 = blockIdx.x * 32, k0 = blockIdx.y * 32;
    const int tx = threadIdx.x, ty = threadIdx.y;
#pragma unroll
    for (int i = 0; i < 32; i += 8)
        t[ty + i][tx] = W[(size_t)(k0 + ty + i) * DD + n0 + tx];
    __syncthreads();
#pragma unroll
    for (int i = 0; i < 32; i += 8) {
        size_t o = (size_t)(n0 + ty + i) * DD + k0 + tx;
        th[o] = __float2half_rn(t[tx][ty + i]);
    }
}

// ---------------- fused fp16 mma.sync GEMM ------------------------------------
// One kernel for all projections. sel = sel_base + blockIdx.x/8:
//   0: x@Wq -> qh/ql   1: x@Wk -> kh/kl   2: x@Wv -> vh   3: ctx@Wo+bias -> outF
// Single-pass fp16 (fp32 accum). CTA 128x128, BK=64, 3-stage cp.async ring.
#define ALD2 72
#define G_MAT2 (128*ALD2)
#define NSTG 16                                 /* 16 stages of K=64 */
#define GEMM_SMEM (2 * 3 * G_MAT2 * 2)          /* 110592 bytes */

__global__ __launch_bounds__(256, 2)
void gemm_fused(const __half* __restrict__ A, const __half* __restrict__ wh,
                const float* __restrict__ bias,
                __half* __restrict__ qh, __half* __restrict__ ql,
                __half* __restrict__ kh, __half* __restrict__ kl,
                __half* __restrict__ vh, float* __restrict__ outF,
                int sel_base)
{
    extern __shared__ char smg[];
    const uint32_t asu = s2u(smg);
    const uint32_t bsu = asu + 3 * G_MAT2 * 2;

    const int t = threadIdx.x;
    const int wid = t >> 5, lane = t & 31;
    const int wm = wid & 1, wn = wid >> 1;
    const int g = lane >> 2, qd = lane & 3;
    const int qd2 = qd * 2;
    const int sel = sel_base + (blockIdx.x >> 3);
    const int n0 = (blockIdx.x & 7) * 128;
    const int m0 = blockIdx.y * 128;

    const __half* B = wh + (size_t)sel * DD * DD;

    const int ld_row = t >> 3;            // 0..31 (+32 per sweep, 4 sweeps)
    const int ld_col = (t & 7) * 8;

    const int a_r = wm*64 + (lane & 15);
    const int a_c = (lane >> 4) * 8;
    const int b_r = wn*32 + (lane & 7) + ((lane >> 4) << 3);
    const int b_c = ((lane >> 3) & 1) * 8;

    float acc[4][4][4];
#pragma unroll
    for (int i = 0; i < 4; i++)
#pragma unroll
        for (int j = 0; j < 4; j++)
#pragma unroll
            for (int e = 0; e < 4; e++) acc[i][j][e] = 0.f;

    auto issue = [&](int s) {
        const int st = s % 3;
        const int kc = s * 64;
#pragma unroll
        for (int i = 0; i < 4; i++) {
            const int row = ld_row + i*32;
            const uint32_t so = (uint32_t)(st*G_MAT2 + row*ALD2 + ld_col) * 2;
            cpa16(asu + so, A + (size_t)(m0 + row) * DD + kc + ld_col);
            cpa16(bsu + so, B + (size_t)(n0 + row) * DD + kc + ld_col);
        }
        cp_commit();
    };

    issue(0);
    issue(1);

    for (int s = 0; s < NSTG; s++) {
        const int st = s % 3;
        if (s == NSTG - 1) cp_wait<0>();
        else               cp_wait<1>();
        __syncthreads();

        const uint32_t ab = asu + (uint32_t)(st*G_MAT2)*2;
        const uint32_t bb = bsu + (uint32_t)(st*G_MAT2)*2;
#pragma unroll
        for (int kk = 0; kk < 4; kk++) {
            uint32_t a[4][4], b4[2][4];
#pragma unroll
            for (int i = 0; i < 4; i++)
                ldsm4(a[i], ab + (uint32_t)((a_r + i*16)*ALD2 + kk*16 + a_c)*2);
#pragma unroll
            for (int jp = 0; jp < 2; jp++)
                ldsm4(b4[jp], bb + (uint32_t)((b_r + jp*16)*ALD2 + kk*16 + b_c)*2);
#pragma unroll
            for (int i = 0; i < 4; i++)
#pragma unroll
                for (int j = 0; j < 4; j++)
                    mma_f16(acc[i][j], a[i], &b4[j >> 1][(j & 1) * 2]);
        }
        if (s + 2 < NSTG) issue(s + 2);
    }

    // epilogue
    __half* oHi = (sel == 0) ? qh : kh;
    __half* oLo = (sel == 0) ? ql : kl;
#pragma unroll
    for (int i = 0; i < 4; i++) {
        const int r1 = m0 + wm*64 + i*16 + g;
        const int r2 = r1 + 8;
#pragma unroll
        for (int j = 0; j < 4; j++) {
            const int col = n0 + wn*32 + j*8 + qd2;
            const float v0 = acc[i][j][0], v1 = acc[i][j][1];
            const float v2 = acc[i][j][2], v3 = acc[i][j][3];
            if (sel == 3) {
                float2 o1, o2;
                o1.x = v0 + bias[col]; o1.y = v1 + bias[col+1];
                o2.x = v2 + bias[col]; o2.y = v3 + bias[col+1];
                *(float2*)(outF + (size_t)r1 * DD + col) = o1;
                *(float2*)(outF + (size_t)r2 * DD + col) = o2;
            } else if (sel == 2) {
                *(__half2*)(vh + (size_t)r1 * DD + col) = __floats2half2_rn(v0, v1);
                *(__half2*)(vh + (size_t)r2 * DD + col) = __floats2half2_rn(v2, v3);
            } else {
                const __half h0 = __float2half_rn(v0), h1 = __float2half_rn(v1);
                const __half h2 = __float2half_rn(v2), h3 = __float2half_rn(v3);
                __half2 hh1, ll1, hh2, ll2;
                hh1.x = h0; hh1.y = h1;
                ll1.x = __float2half_rn(v0 - __half2float(h0));
                ll1.y = __float2half_rn(v1 - __half2float(h1));
                hh2.x = h2; hh2.y = h3;
                ll2.x = __float2half_rn(v2 - __half2float(h2));
                ll2.y = __float2half_rn(v3 - __half2float(h3));
                *(__half2*)(oHi + (size_t)r1 * DD + col) = hh1;
                *(__half2*)(oLo + (size_t)r1 * DD + col) = ll1;
                *(__half2*)(oHi + (size_t)r2 * DD + col) = hh2;
                *(__half2*)(oLo + (size_t)r2 * DD + col) = ll2;
            }
        }
    }
}

// ---------------- causal flash attention (fp16 mma) ---------------------------
// 128 q-rows x 64-key tiles, 256 threads, 2 CTAs/SM. Q register-resident,
// QK^T 3-term fp16 hi/lo split (fp32-accurate scores), PV fp16.
#define FLD 72
#define ST_ONE  (64*FLD*2)                    /* 9216  */
#define ST_BYTES (3*ST_ONE)                   /* 27648 */
#define Q_BYTES (128*FLD*2)                   /* 18432 */
#define FLASH_SMEM (3*ST_BYTES)               /* 82944 >= 2*Q_BYTES */

__global__ __launch_bounds__(256, 2)
void flash_mma(const __half* __restrict__ Qhi, const __half* __restrict__ Qlo,
               const __half* __restrict__ Khi, const __half* __restrict__ Klo,
               const __half* __restrict__ Vh, __half* __restrict__ Ch)
{
    extern __shared__ char smc[];
    const uint32_t smu = s2u(smc);

    const int t = threadIdx.x;
    const int w = t >> 5, lane = t & 31;
    const int g = lane >> 2, qd = lane & 3;
    const int qd2 = qd * 2;
    const int qb = (gridDim.x - 1) - blockIdx.x;   // heavy tiles first
    const int h = blockIdx.y, b = blockIdx.z;

    const size_t qrow0 = (size_t)b * SS + qb * 128;
    const size_t krow0 = (size_t)b * SS;
    const int hc = h * HDIM;
    const int kbmax = 2*qb + 1;

    const int qa_r = 16*w + (lane & 15);
    const int qa_c = (lane >> 4) * 8;
    const int kb_r = (lane & 7) + ((lane >> 4) << 3);
    const int kb_c = ((lane >> 3) & 1) * 8;
    const int v_r  = (lane & 7) + (((lane >> 3) & 1) << 3);
    const int v_c  = (lane >> 4) * 8;

    // ---- Q staging through smem (region reused by KV ring afterwards) ----
#pragma unroll
    for (int i = 0; i < 4; i++) {
        const int idx = t + 256*i;
        const int row = idx >> 3, col = (idx & 7) * 8;
        const uint32_t so = (uint32_t)(row*FLD + col) * 2;
        cpa16(smu + so,           Qhi + (qrow0 + row)*DD + hc + col);
        cpa16(smu + Q_BYTES + so, Qlo + (qrow0 + row)*DD + hc + col);
    }
    cp_commit();
    cp_wait<0>();
    __syncthreads();

    uint32_t qa_h[4][4], qa_l[4][4];
#pragma unroll
    for (int s = 0; s < 4; s++) {
        ldsm4(qa_h[s], smu + (uint32_t)(qa_r*FLD + s*16 + qa_c)*2);
        ldsm4(qa_l[s], smu + Q_BYTES + (uint32_t)(qa_r*FLD + s*16 + qa_c)*2);
    }
    __syncthreads();

    auto issue_kv = [&](int kb) {
        const uint32_t sb = smu + (kb % 3)*ST_BYTES;
#pragma unroll
        for (int i = 0; i < 2; i++) {
            const int idx = t + 256*i;
            const int row = idx >> 3, col = (idx & 7) * 8;
            const uint32_t so = (uint32_t)(row*FLD + col) * 2;
            const size_t gr = (krow0 + kb*64 + row)*DD + hc + col;
            cpa16(sb + so,            Khi + gr);
            cpa16(sb + ST_ONE + so,   Klo + gr);
            cpa16(sb + 2*ST_ONE + so, Vh  + gr);
        }
        cp_commit();
    };
    issue_kv(0);
    issue_kv(1);

    float sc[8][4], o[8][4];
#pragma unroll
    for (int j = 0; j < 8; j++)
#pragma unroll
        for (int e = 0; e < 4; e++) o[j][e] = 0.f;
    const float NEG_INF = __int_as_float(0xff800000u);
    float m0 = NEG_INF, m1 = NEG_INF, l0 = 0.f, l1 = 0.f;

    const int grow0 = qb*128 + 16*w + g;
    const int grow1 = grow0 + 8;
    const int wrow_max = qb*128 + 16*w + 15;

    for (int kb = 0; kb <= kbmax; kb++) {
        const int st = kb % 3;
        if (kb == kbmax) cp_wait<0>();
        else             cp_wait<1>();
        __syncthreads();

        const bool active = (kb*64 <= wrow_max);
        if (active) {
            const uint32_t skh = smu + st*ST_BYTES;
            const uint32_t skl = skh + ST_ONE;
            const uint32_t svb = skh + 2*ST_ONE;

#pragma unroll
            for (int j = 0; j < 8; j++)
#pragma unroll
                for (int e = 0; e < 4; e++) sc[j][e] = 0.f;

#pragma unroll
            for (int s = 0; s < 4; s++) {
#pragma unroll
                for (int jp = 0; jp < 4; jp++) {
                    uint32_t bh[4], bl[4];
                    const uint32_t off =
                        (uint32_t)((jp*16 + kb_r)*FLD + s*16 + kb_c)*2;
                    ldsm4(bh, skh + off);
                    ldsm4(bl, skl + off);
                    mma_f16(sc[2*jp  ], qa_h[s], bh);
                    mma_f16(sc[2*jp+1], qa_h[s], bh + 2);
                    mma_f16(sc[2*jp  ], qa_h[s], bl);
                    mma_f16(sc[2*jp+1], qa_h[s], bl + 2);
                    mma_f16(sc[2*jp  ], qa_l[s], bh);
                    mma_f16(sc[2*jp+1], qa_l[s], bh + 2);
                }
            }

            const bool diag = (kb >= 2*qb);
            float mx0 = NEG_INF, mx1 = NEG_INF;
#pragma unroll
            for (int j = 0; j < 8; j++) {
                const int c0 = kb*64 + j*8 + qd2, c1 = c0 + 1;
                float s0 = sc[j][0]*0.125f, s1 = sc[j][1]*0.125f;
                float s2 = sc[j][2]*0.125f, s3 = sc[j][3]*0.125f;
                if (diag) {
                    if (c0 > grow0) s0 = NEG_INF;
                    if (c1 > grow0) s1 = NEG_INF;
                    if (c0 > grow1) s2 = NEG_INF;
                    if (c1 > grow1) s3 = NEG_INF;
                }
                sc[j][0] = s0; sc[j][1] = s1; sc[j][2] = s2; sc[j][3] = s3;
                mx0 = fmaxf(mx0, fmaxf(s0, s1));
                mx1 = fmaxf(mx1, fmaxf(s2, s3));
            }
            mx0 = fmaxf(mx0, __shfl_xor_sync(0xffffffffu, mx0, 1));
            mx0 = fmaxf(mx0, __shfl_xor_sync(0xffffffffu, mx0, 2));
            mx1 = fmaxf(mx1, __shfl_xor_sync(0xffffffffu, mx1, 1));
            mx1 = fmaxf(mx1, __shfl_xor_sync(0xffffffffu, mx1, 2));

            const float mn0 = fmaxf(m0, mx0), mn1 = fmaxf(m1, mx1);
            const float al0 = __expf(m0 - mn0), al1 = __expf(m1 - mn1);
            m0 = mn0; m1 = mn1;

            float s0sum = 0.f, s1sum = 0.f;
#pragma unroll
            for (int j = 0; j < 8; j++) {
                const float p0 = __expf(sc[j][0] - mn0);
                const float p1 = __expf(sc[j][1] - mn0);
                const float p2 = __expf(sc[j][2] - mn1);
                const float p3 = __expf(sc[j][3] - mn1);
                sc[j][0] = p0; sc[j][1] = p1; sc[j][2] = p2; sc[j][3] = p3;
                s0sum += p0 + p1; s1sum += p2 + p3;
            }
            s0sum += __shfl_xor_sync(0xffffffffu, s0sum, 1);
            s0sum += __shfl_xor_sync(0xffffffffu, s0sum, 2);
            s1sum += __shfl_xor_sync(0xffffffffu, s1sum, 1);
            s1sum += __shfl_xor_sync(0xffffffffu, s1sum, 2);
            l0 = l0 * al0 + s0sum;
            l1 = l1 * al1 + s1sum;

#pragma unroll
            for (int j = 0; j < 8; j++) {
                o[j][0] *= al0; o[j][1] *= al0;
                o[j][2] *= al1; o[j][3] *= al1;
            }

#pragma unroll
            for (int s = 0; s < 4; s++) {
                uint32_t a[4];
                a[0] = h2_as_u32(__floats2half2_rn(sc[2*s  ][0], sc[2*s  ][1]));
                a[1] = h2_as_u32(__floats2half2_rn(sc[2*s  ][2], sc[2*s  ][3]));
                a[2] = h2_as_u32(__floats2half2_rn(sc[2*s+1][0], sc[2*s+1][1]));
                a[3] = h2_as_u32(__floats2half2_rn(sc[2*s+1][2], sc[2*s+1][3]));
#pragma unroll
                for (int jp = 0; jp < 4; jp++) {
                    uint32_t bv[4];
                    ldsm4t(bv, svb + (uint32_t)((s*16 + v_r)*FLD + jp*16 + v_c)*2);
                    mma_f16(o[2*jp  ], a, bv);
                    mma_f16(o[2*jp+1], a, bv + 2);
                }
            }
        }
        if (kb + 2 <= kbmax) issue_kv(kb + 2);
    }

    // ---- epilogue: normalize, single fp16 ctx ----
    const float inv0 = 1.f / l0, inv1 = 1.f / l1;
    const size_t r1 = qrow0 + 16*w + g;
    const size_t r2 = r1 + 8;
#pragma unroll
    for (int j = 0; j < 8; j++) {
        const int col = hc + j*8 + qd2;
        *(__half2*)(Ch + r1*DD + col) =
            __floats2half2_rn(o[j][0]*inv0, o[j][1]*inv0);
        *(__half2*)(Ch + r2*DD + col) =
            __floats2half2_rn(o[j][2]*inv1, o[j][3]*inv1);
    }
}

// ---------------------------------------------------------------------------
extern "C" void kernel_launch(void* const* d_in, const int* in_sizes, int n_in,
                              void* d_out, int out_size)
{
    const float* x  = (const float*)d_in[0];
    const float* Wq = (const float*)d_in[1];
    const float* Wk = (const float*)d_in[2];
    const float* Wv = (const float*)d_in[3];
    const float* Wo = (const float*)d_in[4];
    const float* bo = (const float*)d_in[5];
    float* out = (float*)d_out;

    __half *xh, *qh, *ql, *kh, *kl, *vh, *ch, *wh;
    cudaGetSymbolAddress((void**)&xh, g_xh);
    cudaGetSymbolAddress((void**)&qh, g_qh);
    cudaGetSymbolAddress((void**)&ql, g_ql);
    cudaGetSymbolAddress((void**)&kh, g_kh);
    cudaGetSymbolAddress((void**)&kl, g_kl);
    cudaGetSymbolAddress((void**)&vh, g_vh);
    cudaGetSymbolAddress((void**)&ch, g_ch);
    cudaGetSymbolAddress((void**)&wh, g_wh);

    cudaFuncSetAttribute(gemm_fused,
                         cudaFuncAttributeMaxDynamicSharedMemorySize, GEMM_SMEM);
    cudaFuncSetAttribute(flash_mma,
                         cudaFuncAttributeMaxDynamicSharedMemorySize, FLASH_SMEM);

    // weight transpose + fp16 convert (one launch)
    dim3 wb(32, 8), wg(DD/32, DD/32, 4);
    wtrans4_kernel<<<wg, wb>>>(Wq, Wk, Wv, Wo, wh);

    // x -> fp16
    const int n4 = MROWS * DD / 4;
    xhalf_kernel<<<n4 / 256, 256>>>((const float4*)x, (__half2*)xh, n4);

    // fused QKV projections (one launch)
    dim3 gq(3 * DD / 128, MROWS / 128);   // (24, 64)
    gemm_fused<<<gq, 256, GEMM_SMEM>>>(xh, wh, nullptr,
                                       qh, ql, kh, kl, vh, nullptr, 0);

    // attention
    dim3 gf(SS / 128, NH, BB);            // (16, 16, 4)
    flash_mma<<<gf, 256, FLASH_SMEM>>>(qh, ql, kh, kl, vh, ch);

    // output projection + bias
    dim3 go(DD / 128, MROWS / 128);       // (8, 64)
    gemm_fused<<<go, 256, GEMM_SMEM>>>(ch, wh, bo,
                                       nullptr, nullptr, nullptr, nullptr,
                                       nullptr, out, 3);
}

// round 10
// speedup vs baseline: 9.4631x; 1.1200x over previous
#include <cuda_runtime.h>
#include <cuda_bf16.h>
#include <cuda_fp16.h>
#include <math.h>
#include <stdint.h>

#define BB 4
#define SS 2048
#define DD 1024
#define NH 16
#define HDIM 64
#define MROWS (BB*SS)   /* 8192 */

// ---------------- scratch (__device__ globals; allocs forbidden) ------------
__device__ __half g_xh[MROWS*DD];
__device__ __half g_qh[MROWS*DD];
__device__ __half g_kh[MROWS*DD];
__device__ __half g_kl[MROWS*DD];
__device__ __half g_vh[MROWS*DD];
__device__ __half g_ch[MROWS*DD];
__device__ __half g_wh[4][DD*DD];   // transposed fp16: [Wq, Wk, Wv, Wo]

// ---------------- ptx helpers -------------------------------------------------
static __device__ __forceinline__ void mma_f16(float* c, const uint32_t* a,
                                               const uint32_t* b) {
    asm volatile(
        "mma.sync.aligned.m16n8k16.row.col.f32.f16.f16.f32 "
        "{%0,%1,%2,%3}, {%4,%5,%6,%7}, {%8,%9}, {%0,%1,%2,%3};"
        : "+f"(c[0]), "+f"(c[1]), "+f"(c[2]), "+f"(c[3])
        : "r"(a[0]), "r"(a[1]), "r"(a[2]), "r"(a[3]), "r"(b[0]), "r"(b[1]));
}
static __device__ __forceinline__ void ldsm4(uint32_t* r, uint32_t a) {
    asm volatile("ldmatrix.sync.aligned.m8n8.x4.shared.b16 {%0,%1,%2,%3}, [%4];"
                 : "=r"(r[0]), "=r"(r[1]), "=r"(r[2]), "=r"(r[3]) : "r"(a));
}
static __device__ __forceinline__ void ldsm4t(uint32_t* r, uint32_t a) {
    asm volatile("ldmatrix.sync.aligned.m8n8.x4.trans.shared.b16 {%0,%1,%2,%3}, [%4];"
                 : "=r"(r[0]), "=r"(r[1]), "=r"(r[2]), "=r"(r[3]) : "r"(a));
}
static __device__ __forceinline__ uint32_t s2u(const void* p) {
    uint32_t a;
    asm("{ .reg .u64 t; cvta.to.shared.u64 t, %1; cvt.u32.u64 %0, t; }"
        : "=r"(a) : "l"(p));
    return a;
}
static __device__ __forceinline__ void cpa16(uint32_t dst, const void* src) {
    asm volatile("cp.async.cg.shared.global [%0], [%1], 16;"
                 :: "r"(dst), "l"(src));
}
static __device__ __forceinline__ void cp_commit() {
    asm volatile("cp.async.commit_group;");
}
template<int N>
static __device__ __forceinline__ void cp_wait() {
    asm volatile("cp.async.wait_group %0;" :: "n"(N));
}
static __device__ __forceinline__ uint32_t h2_as_u32(__half2 v) {
    union { __half2 h; uint32_t u; } cvt;
    cvt.h = v;
    return cvt.u;
}

// ---------------- convert / transpose kernels --------------------------------
__global__ void xhalf_kernel(const float4* __restrict__ x,
                             __half2* __restrict__ xh, int n4)
{
    int i = blockIdx.x * blockDim.x + threadIdx.x;
    if (i >= n4) return;
    float4 v = x[i];
    xh[2*i]   = __floats2half2_rn(v.x, v.y);
    xh[2*i+1] = __floats2half2_rn(v.z, v.w);
}

__global__ void wtrans4_kernel(const float* __restrict__ W0,
                               const float* __restrict__ W1,
                               const float* __restrict__ W2,
                               const float* __restrict__ W3,
                               __half* __restrict__ wh)
{
    __shared__ float t[32][33];
    const float* Ws[4] = {W0, W1, W2, W3};
    const int z = blockIdx.z;
    const float* W = Ws[z];
    __half* th = wh + (size_t)z * DD * DD;

    const int n0 = blockIdx.x * 32, k0 = blockIdx.y * 32;
    const int tx = threadIdx.x, ty = threadIdx.y;
#pragma unroll
    for (int i = 0; i < 32; i += 8)
        t[ty + i][tx] = W[(size_t)(k0 + ty + i) * DD + n0 + tx];
    __syncthreads();
#pragma unroll
    for (int i = 0; i < 32; i += 8) {
        size_t o = (size_t)(n0 + ty + i) * DD + k0 + tx;
        th[o] = __float2half_rn(t[tx][ty + i]);
    }
}

// ---------------- fused fp16 mma.sync GEMM ------------------------------------
// sel = sel_base + blockIdx.x/8:
//   0: x@Wq -> qh   1: x@Wk -> kh/kl   2: x@Wv -> vh   3: ctx@Wo+bias -> outF
#define ALD2 72
#define G_MAT2 (128*ALD2)
#define NSTG 16
#define GEMM_SMEM (2 * 3 * G_MAT2 * 2)          /* 110592 bytes */

__global__ __launch_bounds__(256, 2)
void gemm_fused(const __half* __restrict__ A, const __half* __restrict__ wh,
                const float* __restrict__ bias,
                __half* __restrict__ qh,
                __half* __restrict__ kh, __half* __restrict__ kl,
                __half* __restrict__ vh, float* __restrict__ outF,
                int sel_base)
{
    extern __shared__ char smg[];
    const uint32_t asu = s2u(smg);
    const uint32_t bsu = asu + 3 * G_MAT2 * 2;

    const int t = threadIdx.x;
    const int wid = t >> 5, lane = t & 31;
    const int wm = wid & 1, wn = wid >> 1;
    const int g = lane >> 2, qd = lane & 3;
    const int qd2 = qd * 2;
    const int sel = sel_base + (blockIdx.x >> 3);
    const int n0 = (blockIdx.x & 7) * 128;
    const int m0 = blockIdx.y * 128;

    const __half* B = wh + (size_t)sel * DD * DD;

    const int ld_row = t >> 3;
    const int ld_col = (t & 7) * 8;

    const int a_r = wm*64 + (lane & 15);
    const int a_c = (lane >> 4) * 8;
    const int b_r = wn*32 + (lane & 7) + ((lane >> 4) << 3);
    const int b_c = ((lane >> 3) & 1) * 8;

    float acc[4][4][4];
#pragma unroll
    for (int i = 0; i < 4; i++)
#pragma unroll
        for (int j = 0; j < 4; j++)
#pragma unroll
            for (int e = 0; e < 4; e++) acc[i][j][e] = 0.f;

    auto issue = [&](int s) {
        const int st = s % 3;
        const int kc = s * 64;
#pragma unroll
        for (int i = 0; i < 4; i++) {
            const int row = ld_row + i*32;
            const uint32_t so = (uint32_t)(st*G_MAT2 + row*ALD2 + ld_col) * 2;
            cpa16(asu + so, A + (size_t)(m0 + row) * DD + kc + ld_col);
            cpa16(bsu + so, B + (size_t)(n0 + row) * DD + kc + ld_col);
        }
        cp_commit();
    };

    issue(0);
    issue(1);

    for (int s = 0; s < NSTG; s++) {
        const int st = s % 3;
        if (s == NSTG - 1) cp_wait<0>();
        else               cp_wait<1>();
        __syncthreads();

        const uint32_t ab = asu + (uint32_t)(st*G_MAT2)*2;
        const uint32_t bb = bsu + (uint32_t)(st*G_MAT2)*2;
#pragma unroll
        for (int kk = 0; kk < 4; kk++) {
            uint32_t a[4][4], b4[2][4];
#pragma unroll
            for (int i = 0; i < 4; i++)
                ldsm4(a[i], ab + (uint32_t)((a_r + i*16)*ALD2 + kk*16 + a_c)*2);
#pragma unroll
            for (int jp = 0; jp < 2; jp++)
                ldsm4(b4[jp], bb + (uint32_t)((b_r + jp*16)*ALD2 + kk*16 + b_c)*2);
#pragma unroll
            for (int i = 0; i < 4; i++)
#pragma unroll
                for (int j = 0; j < 4; j++)
                    mma_f16(acc[i][j], a[i], &b4[j >> 1][(j & 1) * 2]);
        }
        if (s + 2 < NSTG) issue(s + 2);
    }

    // epilogue
#pragma unroll
    for (int i = 0; i < 4; i++) {
        const int r1 = m0 + wm*64 + i*16 + g;
        const int r2 = r1 + 8;
#pragma unroll
        for (int j = 0; j < 4; j++) {
            const int col = n0 + wn*32 + j*8 + qd2;
            const float v0 = acc[i][j][0], v1 = acc[i][j][1];
            const float v2 = acc[i][j][2], v3 = acc[i][j][3];
            if (sel == 3) {
                float2 o1, o2;
                o1.x = v0 + bias[col]; o1.y = v1 + bias[col+1];
                o2.x = v2 + bias[col]; o2.y = v3 + bias[col+1];
                *(float2*)(outF + (size_t)r1 * DD + col) = o1;
                *(float2*)(outF + (size_t)r2 * DD + col) = o2;
            } else if (sel == 2) {
                *(__half2*)(vh + (size_t)r1 * DD + col) = __floats2half2_rn(v0, v1);
                *(__half2*)(vh + (size_t)r2 * DD + col) = __floats2half2_rn(v2, v3);
            } else if (sel == 0) {
                *(__half2*)(qh + (size_t)r1 * DD + col) = __floats2half2_rn(v0, v1);
                *(__half2*)(qh + (size_t)r2 * DD + col) = __floats2half2_rn(v2, v3);
            } else {
                const __half h0 = __float2half_rn(v0), h1 = __float2half_rn(v1);
                const __half h2 = __float2half_rn(v2), h3 = __float2half_rn(v3);
                __half2 hh1, ll1, hh2, ll2;
                hh1.x = h0; hh1.y = h1;
                ll1.x = __float2half_rn(v0 - __half2float(h0));
                ll1.y = __float2half_rn(v1 - __half2float(h1));
                hh2.x = h2; hh2.y = h3;
                ll2.x = __float2half_rn(v2 - __half2float(h2));
                ll2.y = __float2half_rn(v3 - __half2float(h3));
                *(__half2*)(kh + (size_t)r1 * DD + col) = hh1;
                *(__half2*)(kl + (size_t)r1 * DD + col) = ll1;
                *(__half2*)(kh + (size_t)r2 * DD + col) = hh2;
                *(__half2*)(kl + (size_t)r2 * DD + col) = ll2;
            }
        }
    }
}

// ---------------- causal flash attention (fp16 mma, 2-term QK) ----------------
// 128 q-rows x 64-key tiles, 256 threads, 2 CTAs/SM. Q single fp16 in regs;
// scores = qh.(khi + klo) fp32-accum; softmax in exp2 domain; PV fp16.
#define FLD 72
#define ST_ONE  (64*FLD*2)                    /* 9216  */
#define ST_BYTES (3*ST_ONE)                   /* 27648 */
#define FLASH_SMEM (3*ST_BYTES)               /* 82944 */
#define SC_SCALE 0.180336880f                 /* 0.125 * log2(e) */

__global__ __launch_bounds__(256, 2)
void flash_mma(const __half* __restrict__ Qh,
               const __half* __restrict__ Khi, const __half* __restrict__ Klo,
               const __half* __restrict__ Vh, __half* __restrict__ Ch)
{
    extern __shared__ char smc[];
    const uint32_t smu = s2u(smc);

    const int t = threadIdx.x;
    const int w = t >> 5, lane = t & 31;
    const int g = lane >> 2, qd = lane & 3;
    const int qd2 = qd * 2;
    const int qb = (gridDim.x - 1) - blockIdx.x;
    const int h = blockIdx.y, b = blockIdx.z;

    const size_t qrow0 = (size_t)b * SS + qb * 128;
    const size_t krow0 = (size_t)b * SS;
    const int hc = h * HDIM;
    const int kbmax = 2*qb + 1;

    const int qa_r = 16*w + (lane & 15);
    const int qa_c = (lane >> 4) * 8;
    const int kb_r = (lane & 7) + ((lane >> 4) << 3);
    const int kb_c = ((lane >> 3) & 1) * 8;
    const int v_r  = (lane & 7) + (((lane >> 3) & 1) << 3);
    const int v_c  = (lane >> 4) * 8;

    // ---- Q staging: 128 rows x 128 B = 1024 chunks of 16B (4 sweeps) ----
#pragma unroll
    for (int i = 0; i < 4; i++) {
        const int idx = t + 256*i;              // 0..1023
        const int row = idx >> 3, col = (idx & 7) * 8;
        cpa16(smu + (uint32_t)(row*FLD + col)*2, Qh + (qrow0 + row)*DD + hc + col);
    }
    cp_commit();
    cp_wait<0>();
    __syncthreads();

    uint32_t qa[4][4];
#pragma unroll
    for (int s = 0; s < 4; s++)
        ldsm4(qa[s], smu + (uint32_t)(qa_r*FLD + s*16 + qa_c)*2);
    __syncthreads();

    auto issue_kv = [&](int kb) {
        const uint32_t sb = smu + (kb % 3)*ST_BYTES;
#pragma unroll
        for (int i = 0; i < 2; i++) {
            const int idx = t + 256*i;
            const int row = idx >> 3, col = (idx & 7) * 8;
            const uint32_t so = (uint32_t)(row*FLD + col) * 2;
            const size_t gr = (krow0 + kb*64 + row)*DD + hc + col;
            cpa16(sb + so,            Khi + gr);
            cpa16(sb + ST_ONE + so,   Klo + gr);
            cpa16(sb + 2*ST_ONE + so, Vh  + gr);
        }
        cp_commit();
    };
    issue_kv(0);
    issue_kv(1);

    float sc[8][4], o[8][4];
#pragma unroll
    for (int j = 0; j < 8; j++)
#pragma unroll
        for (int e = 0; e < 4; e++) o[j][e] = 0.f;
    const float NEG_INF = __int_as_float(0xff800000u);
    float m0 = NEG_INF, m1 = NEG_INF, l0 = 0.f, l1 = 0.f;

    const int grow0 = qb*128 + 16*w + g;
    const int grow1 = grow0 + 8;
    const int wrow_max = qb*128 + 16*w + 15;

    for (int kb = 0; kb <= kbmax; kb++) {
        const int st = kb % 3;
        if (kb == kbmax) cp_wait<0>();
        else             cp_wait<1>();
        __syncthreads();

        const bool active = (kb*64 <= wrow_max);
        if (active) {
            const uint32_t skh = smu + st*ST_BYTES;
            const uint32_t skl = skh + ST_ONE;
            const uint32_t svb = skh + 2*ST_ONE;

#pragma unroll
            for (int j = 0; j < 8; j++)
#pragma unroll
                for (int e = 0; e < 4; e++) sc[j][e] = 0.f;

#pragma unroll
            for (int s = 0; s < 4; s++) {
#pragma unroll
                for (int jp = 0; jp < 4; jp++) {
                    uint32_t bh[4], bl[4];
                    const uint32_t off =
                        (uint32_t)((jp*16 + kb_r)*FLD + s*16 + kb_c)*2;
                    ldsm4(bh, skh + off);
                    ldsm4(bl, skl + off);
                    mma_f16(sc[2*jp  ], qa[s], bh);
                    mma_f16(sc[2*jp+1], qa[s], bh + 2);
                    mma_f16(sc[2*jp  ], qa[s], bl);
                    mma_f16(sc[2*jp+1], qa[s], bl + 2);
                }
            }

            // ---- scale (exp2 domain) + causal mask + online softmax ----
            const bool diag = (kb >= 2*qb);
            float mx0 = NEG_INF, mx1 = NEG_INF;
#pragma unroll
            for (int j = 0; j < 8; j++) {
                const int c0 = kb*64 + j*8 + qd2, c1 = c0 + 1;
                float s0 = sc[j][0]*SC_SCALE, s1 = sc[j][1]*SC_SCALE;
                float s2 = sc[j][2]*SC_SCALE, s3 = sc[j][3]*SC_SCALE;
                if (diag) {
                    if (c0 > grow0) s0 = NEG_INF;
                    if (c1 > grow0) s1 = NEG_INF;
                    if (c0 > grow1) s2 = NEG_INF;
                    if (c1 > grow1) s3 = NEG_INF;
                }
                sc[j][0] = s0; sc[j][1] = s1; sc[j][2] = s2; sc[j][3] = s3;
                mx0 = fmaxf(mx0, fmaxf(s0, s1));
                mx1 = fmaxf(mx1, fmaxf(s2, s3));
            }
            mx0 = fmaxf(mx0, __shfl_xor_sync(0xffffffffu, mx0, 1));
            mx0 = fmaxf(mx0, __shfl_xor_sync(0xffffffffu, mx0, 2));
            mx1 = fmaxf(mx1, __shfl_xor_sync(0xffffffffu, mx1, 1));
            mx1 = fmaxf(mx1, __shfl_xor_sync(0xffffffffu, mx1, 2));

            const float mn0 = fmaxf(m0, mx0), mn1 = fmaxf(m1, mx1);
            const float al0 = exp2f(m0 - mn0), al1 = exp2f(m1 - mn1);
            m0 = mn0; m1 = mn1;

            float s0sum = 0.f, s1sum = 0.f;
#pragma unroll
            for (int j = 0; j < 8; j++) {
                const float p0 = exp2f(sc[j][0] - mn0);
                const float p1 = exp2f(sc[j][1] - mn0);
                const float p2 = exp2f(sc[j][2] - mn1);
                const float p3 = exp2f(sc[j][3] - mn1);
                sc[j][0] = p0; sc[j][1] = p1; sc[j][2] = p2; sc[j][3] = p3;
                s0sum += p0 + p1; s1sum += p2 + p3;
            }
            s0sum += __shfl_xor_sync(0xffffffffu, s0sum, 1);
            s0sum += __shfl_xor_sync(0xffffffffu, s0sum, 2);
            s1sum += __shfl_xor_sync(0xffffffffu, s1sum, 1);
            s1sum += __shfl_xor_sync(0xffffffffu, s1sum, 2);
            l0 = l0 * al0 + s0sum;
            l1 = l1 * al1 + s1sum;

#pragma unroll
            for (int j = 0; j < 8; j++) {
                o[j][0] *= al0; o[j][1] *= al0;
                o[j][2] *= al1; o[j][3] *= al1;
            }

            // ---- o += P @ V ----
#pragma unroll
            for (int s = 0; s < 4; s++) {
                uint32_t a[4];
                a[0] = h2_as_u32(__floats2half2_rn(sc[2*s  ][0], sc[2*s  ][1]));
                a[1] = h2_as_u32(__floats2half2_rn(sc[2*s  ][2], sc[2*s  ][3]));
                a[2] = h2_as_u32(__floats2half2_rn(sc[2*s+1][0], sc[2*s+1][1]));
                a[3] = h2_as_u32(__floats2half2_rn(sc[2*s+1][2], sc[2*s+1][3]));
#pragma unroll
                for (int jp = 0; jp < 4; jp++) {
                    uint32_t bv[4];
                    ldsm4t(bv, svb + (uint32_t)((s*16 + v_r)*FLD + jp*16 + v_c)*2);
                    mma_f16(o[2*jp  ], a, bv);
                    mma_f16(o[2*jp+1], a, bv + 2);
                }
            }
        }
        if (kb + 2 <= kbmax) issue_kv(kb + 2);
    }

    // ---- epilogue ----
    const float inv0 = 1.f / l0, inv1 = 1.f / l1;
    const size_t r1 = qrow0 + 16*w + g;
    const size_t r2 = r1 + 8;
#pragma unroll
    for (int j = 0; j < 8; j++) {
        const int col = hc + j*8 + qd2;
        *(__half2*)(Ch + r1*DD + col) =
            __floats2half2_rn(o[j][0]*inv0, o[j][1]*inv0);
        *(__half2*)(Ch + r2*DD + col) =
            __floats2half2_rn(o[j][2]*inv1, o[j][3]*inv1);
    }
}

// ---------------------------------------------------------------------------
extern "C" void kernel_launch(void* const* d_in, const int* in_sizes, int n_in,
                              void* d_out, int out_size)
{
    const float* x  = (const float*)d_in[0];
    const float* Wq = (const float*)d_in[1];
    const float* Wk = (const float*)d_in[2];
    const float* Wv = (const float*)d_in[3];
    const float* Wo = (const float*)d_in[4];
    const float* bo = (const float*)d_in[5];
    float* out = (float*)d_out;

    __half *xh, *qh, *kh, *kl, *vh, *ch, *wh;
    cudaGetSymbolAddress((void**)&xh, g_xh);
    cudaGetSymbolAddress((void**)&qh, g_qh);
    cudaGetSymbolAddress((void**)&kh, g_kh);
    cudaGetSymbolAddress((void**)&kl, g_kl);
    cudaGetSymbolAddress((void**)&vh, g_vh);
    cudaGetSymbolAddress((void**)&ch, g_ch);
    cudaGetSymbolAddress((void**)&wh, g_wh);

    cudaFuncSetAttribute(gemm_fused,
                         cudaFuncAttributeMaxDynamicSharedMemorySize, GEMM_SMEM);
    cudaFuncSetAttribute(flash_mma,
                         cudaFuncAttributeMaxDynamicSharedMemorySize, FLASH_SMEM);

    // weight transpose + fp16 convert
    dim3 wb(32, 8), wg(DD/32, DD/32, 4);
    wtrans4_kernel<<<wg, wb>>>(Wq, Wk, Wv, Wo, wh);

    // x -> fp16
    const int n4 = MROWS * DD / 4;
    xhalf_kernel<<<n4 / 256, 256>>>((const float4*)x, (__half2*)xh, n4);

    // fused QKV projections
    dim3 gq(3 * DD / 128, MROWS / 128);   // (24, 64)
    gemm_fused<<<gq, 256, GEMM_SMEM>>>(xh, wh, nullptr,
                                       qh, kh, kl, vh, nullptr, 0);

    // attention
    dim3 gf(SS / 128, NH, BB);            // (16, 16, 4)
    flash_mma<<<gf, 256, FLASH_SMEM>>>(qh, kh, kl, vh, ch);

    // output projection + bias
    dim3 go(DD / 128, MROWS / 128);       // (8, 64)
    gemm_fused<<<go, 256, GEMM_SMEM>>>(ch, wh, bo,
                                       nullptr, nullptr, nullptr,
                                       nullptr, out, 3);
}

// round 11
// speedup vs baseline: 10.6604x; 1.1265x over previous
#include <cuda_runtime.h>
#include <cuda_bf16.h>
#include <cuda_fp16.h>
#include <math.h>
#include <stdint.h>

#define BB 4
#define SS 2048
#define DD 1024
#define NH 16
#define HDIM 64
#define MROWS (BB*SS)   /* 8192 */

// ---------------- scratch (__device__ globals; allocs forbidden) ------------
__device__ __half g_xh[MROWS*DD];
__device__ __half g_qh[MROWS*DD];
__device__ __half g_kh[MROWS*DD];
__device__ __half g_vh[MROWS*DD];
__device__ __half g_ch[MROWS*DD];
__device__ __half g_wh[4][DD*DD];   // transposed fp16: [Wq, Wk, Wv, Wo]

// ---------------- ptx helpers -------------------------------------------------
static __device__ __forceinline__ void mma_f16(float* c, const uint32_t* a,
                                               const uint32_t* b) {
    asm volatile(
        "mma.sync.aligned.m16n8k16.row.col.f32.f16.f16.f32 "
        "{%0,%1,%2,%3}, {%4,%5,%6,%7}, {%8,%9}, {%0,%1,%2,%3};"
        : "+f"(c[0]), "+f"(c[1]), "+f"(c[2]), "+f"(c[3])
        : "r"(a[0]), "r"(a[1]), "r"(a[2]), "r"(a[3]), "r"(b[0]), "r"(b[1]));
}
static __device__ __forceinline__ void ldsm4(uint32_t* r, uint32_t a) {
    asm volatile("ldmatrix.sync.aligned.m8n8.x4.shared.b16 {%0,%1,%2,%3}, [%4];"
                 : "=r"(r[0]), "=r"(r[1]), "=r"(r[2]), "=r"(r[3]) : "r"(a));
}
static __device__ __forceinline__ void ldsm4t(uint32_t* r, uint32_t a) {
    asm volatile("ldmatrix.sync.aligned.m8n8.x4.trans.shared.b16 {%0,%1,%2,%3}, [%4];"
                 : "=r"(r[0]), "=r"(r[1]), "=r"(r[2]), "=r"(r[3]) : "r"(a));
}
static __device__ __forceinline__ uint32_t s2u(const void* p) {
    uint32_t a;
    asm("{ .reg .u64 t; cvta.to.shared.u64 t, %1; cvt.u32.u64 %0, t; }"
        : "=r"(a) : "l"(p));
    return a;
}
static __device__ __forceinline__ void cpa16(uint32_t dst, const void* src) {
    asm volatile("cp.async.cg.shared.global [%0], [%1], 16;"
                 :: "r"(dst), "l"(src));
}
static __device__ __forceinline__ void cp_commit() {
    asm volatile("cp.async.commit_group;");
}
template<int N>
static __device__ __forceinline__ void cp_wait() {
    asm volatile("cp.async.wait_group %0;" :: "n"(N));
}
static __device__ __forceinline__ uint32_t h2_as_u32(__half2 v) {
    union { __half2 h; uint32_t u; } cvt;
    cvt.h = v;
    return cvt.u;
}

// ---------------- convert / transpose kernels --------------------------------
__global__ void xhalf_kernel(const float4* __restrict__ x,
                             __half2* __restrict__ xh, int n4)
{
    int i = blockIdx.x * blockDim.x + threadIdx.x;
    if (i >= n4) return;
    float4 v = x[i];
    xh[2*i]   = __floats2half2_rn(v.x, v.y);
    xh[2*i+1] = __floats2half2_rn(v.z, v.w);
}

__global__ void wtrans4_kernel(const float* __restrict__ W0,
                               const float* __restrict__ W1,
                               const float* __restrict__ W2,
                               const float* __restrict__ W3,
                               __half* __restrict__ wh)
{
    __shared__ float t[32][33];
    const float* Ws[4] = {W0, W1, W2, W3};
    const int z = blockIdx.z;
    const float* W = Ws[z];
    __half* th = wh + (size_t)z * DD * DD;

    const int n0 = blockIdx.x * 32, k0 = blockIdx.y * 32;
    const int tx = threadIdx.x, ty = threadIdx.y;
#pragma unroll
    for (int i = 0; i < 32; i += 8)
        t[ty + i][tx] = W[(size_t)(k0 + ty + i) * DD + n0 + tx];
    __syncthreads();
#pragma unroll
    for (int i = 0; i < 32; i += 8) {
        size_t o = (size_t)(n0 + ty + i) * DD + k0 + tx;
        th[o] = __float2half_rn(t[tx][ty + i]);
    }
}

// ---------------- fused fp16 mma.sync GEMM ------------------------------------
// sel = sel_base + blockIdx.x/8:
//   0: x@Wq -> qh   1: x@Wk -> kh   2: x@Wv -> vh   3: ctx@Wo+bias -> outF
#define ALD2 72
#define G_MAT2 (128*ALD2)
#define NSTG 16
#define GEMM_SMEM (2 * 3 * G_MAT2 * 2)          /* 110592 bytes */

__global__ __launch_bounds__(256, 2)
void gemm_fused(const __half* __restrict__ A, const __half* __restrict__ wh,
                const float* __restrict__ bias,
                __half* __restrict__ qh, __half* __restrict__ kh,
                __half* __restrict__ vh, float* __restrict__ outF,
                int sel_base)
{
    extern __shared__ char smg[];
    const uint32_t asu = s2u(smg);
    const uint32_t bsu = asu + 3 * G_MAT2 * 2;

    const int t = threadIdx.x;
    const int wid = t >> 5, lane = t & 31;
    const int wm = wid & 1, wn = wid >> 1;
    const int g = lane >> 2, qd = lane & 3;
    const int qd2 = qd * 2;
    const int sel = sel_base + (blockIdx.x >> 3);
    const int n0 = (blockIdx.x & 7) * 128;
    const int m0 = blockIdx.y * 128;

    const __half* B = wh + (size_t)sel * DD * DD;

    const int ld_row = t >> 3;
    const int ld_col = (t & 7) * 8;

    const int a_r = wm*64 + (lane & 15);
    const int a_c = (lane >> 4) * 8;
    const int b_r = wn*32 + (lane & 7) + ((lane >> 4) << 3);
    const int b_c = ((lane >> 3) & 1) * 8;

    float acc[4][4][4];
#pragma unroll
    for (int i = 0; i < 4; i++)
#pragma unroll
        for (int j = 0; j < 4; j++)
#pragma unroll
            for (int e = 0; e < 4; e++) acc[i][j][e] = 0.f;

    auto issue = [&](int s) {
        const int st = s % 3;
        const int kc = s * 64;
#pragma unroll
        for (int i = 0; i < 4; i++) {
            const int row = ld_row + i*32;
            const uint32_t so = (uint32_t)(st*G_MAT2 + row*ALD2 + ld_col) * 2;
            cpa16(asu + so, A + (size_t)(m0 + row) * DD + kc + ld_col);
            cpa16(bsu + so, B + (size_t)(n0 + row) * DD + kc + ld_col);
        }
        cp_commit();
    };

    issue(0);
    issue(1);

    for (int s = 0; s < NSTG; s++) {
        const int st = s % 3;
        if (s == NSTG - 1) cp_wait<0>();
        else               cp_wait<1>();
        __syncthreads();

        const uint32_t ab = asu + (uint32_t)(st*G_MAT2)*2;
        const uint32_t bb = bsu + (uint32_t)(st*G_MAT2)*2;
#pragma unroll
        for (int kk = 0; kk < 4; kk++) {
            uint32_t a[4][4], b4[2][4];
#pragma unroll
            for (int i = 0; i < 4; i++)
                ldsm4(a[i], ab + (uint32_t)((a_r + i*16)*ALD2 + kk*16 + a_c)*2);
#pragma unroll
            for (int jp = 0; jp < 2; jp++)
                ldsm4(b4[jp], bb + (uint32_t)((b_r + jp*16)*ALD2 + kk*16 + b_c)*2);
#pragma unroll
            for (int i = 0; i < 4; i++)
#pragma unroll
                for (int j = 0; j < 4; j++)
                    mma_f16(acc[i][j], a[i], &b4[j >> 1][(j & 1) * 2]);
        }
        if (s + 2 < NSTG) issue(s + 2);
    }

    // epilogue
    __half* oH = (sel == 0) ? qh : ((sel == 1) ? kh : vh);
#pragma unroll
    for (int i = 0; i < 4; i++) {
        const int r1 = m0 + wm*64 + i*16 + g;
        const int r2 = r1 + 8;
#pragma unroll
        for (int j = 0; j < 4; j++) {
            const int col = n0 + wn*32 + j*8 + qd2;
            const float v0 = acc[i][j][0], v1 = acc[i][j][1];
            const float v2 = acc[i][j][2], v3 = acc[i][j][3];
            if (sel == 3) {
                float2 o1, o2;
                o1.x = v0 + bias[col]; o1.y = v1 + bias[col+1];
                o2.x = v2 + bias[col]; o2.y = v3 + bias[col+1];
                *(float2*)(outF + (size_t)r1 * DD + col) = o1;
                *(float2*)(outF + (size_t)r2 * DD + col) = o2;
            } else {
                *(__half2*)(oH + (size_t)r1 * DD + col) = __floats2half2_rn(v0, v1);
                *(__half2*)(oH + (size_t)r2 * DD + col) = __floats2half2_rn(v2, v3);
            }
        }
    }
}

// ---------------- causal flash attention (fp16 mma, single-term QK) -----------
// 128 q-rows x 64-key tiles, 256 threads, 2 CTAs/SM. Q single fp16 in regs;
// scores = qh.kh fp32-accum; softmax in exp2 domain; PV fp16.
#define FLD 72
#define ST_ONE  (64*FLD*2)                    /* 9216  */
#define ST_BYTES (2*ST_ONE)                   /* 18432: K + V per stage */
#define FLASH_SMEM (3*ST_BYTES)               /* 55296 */
#define SC_SCALE 0.180336880f                 /* 0.125 * log2(e) */

__global__ __launch_bounds__(256, 2)
void flash_mma(const __half* __restrict__ Qh, const __half* __restrict__ Kh,
               const __half* __restrict__ Vh, __half* __restrict__ Ch)
{
    extern __shared__ char smc[];
    const uint32_t smu = s2u(smc);

    const int t = threadIdx.x;
    const int w = t >> 5, lane = t & 31;
    const int g = lane >> 2, qd = lane & 3;
    const int qd2 = qd * 2;
    const int qb = (gridDim.x - 1) - blockIdx.x;
    const int h = blockIdx.y, b = blockIdx.z;

    const size_t qrow0 = (size_t)b * SS + qb * 128;
    const size_t krow0 = (size_t)b * SS;
    const int hc = h * HDIM;
    const int kbmax = 2*qb + 1;

    const int qa_r = 16*w + (lane & 15);
    const int qa_c = (lane >> 4) * 8;
    const int kb_r = (lane & 7) + ((lane >> 4) << 3);
    const int kb_c = ((lane >> 3) & 1) * 8;
    const int v_r  = (lane & 7) + (((lane >> 3) & 1) << 3);
    const int v_c  = (lane >> 4) * 8;

    // ---- Q staging: 128 rows x 128 B = 1024 chunks of 16B (4 sweeps) ----
#pragma unroll
    for (int i = 0; i < 4; i++) {
        const int idx = t + 256*i;              // 0..1023
        const int row = idx >> 3, col = (idx & 7) * 8;
        cpa16(smu + (uint32_t)(row*FLD + col)*2, Qh + (qrow0 + row)*DD + hc + col);
    }
    cp_commit();
    cp_wait<0>();
    __syncthreads();

    uint32_t qa[4][4];
#pragma unroll
    for (int s = 0; s < 4; s++)
        ldsm4(qa[s], smu + (uint32_t)(qa_r*FLD + s*16 + qa_c)*2);
    __syncthreads();

    auto issue_kv = [&](int kb) {
        const uint32_t sb = smu + (kb % 3)*ST_BYTES;
#pragma unroll
        for (int i = 0; i < 2; i++) {
            const int idx = t + 256*i;
            const int row = idx >> 3, col = (idx & 7) * 8;
            const uint32_t so = (uint32_t)(row*FLD + col) * 2;
            const size_t gr = (krow0 + kb*64 + row)*DD + hc + col;
            cpa16(sb + so,          Kh + gr);
            cpa16(sb + ST_ONE + so, Vh + gr);
        }
        cp_commit();
    };
    issue_kv(0);
    issue_kv(1);

    float sc[8][4], o[8][4];
#pragma unroll
    for (int j = 0; j < 8; j++)
#pragma unroll
        for (int e = 0; e < 4; e++) o[j][e] = 0.f;
    const float NEG_INF = __int_as_float(0xff800000u);
    float m0 = NEG_INF, m1 = NEG_INF, l0 = 0.f, l1 = 0.f;

    const int grow0 = qb*128 + 16*w + g;
    const int grow1 = grow0 + 8;
    const int wrow_max = qb*128 + 16*w + 15;

    for (int kb = 0; kb <= kbmax; kb++) {
        const int st = kb % 3;
        if (kb == kbmax) cp_wait<0>();
        else             cp_wait<1>();
        __syncthreads();

        const bool active = (kb*64 <= wrow_max);
        if (active) {
            const uint32_t skh = smu + st*ST_BYTES;
            const uint32_t svb = skh + ST_ONE;

#pragma unroll
            for (int j = 0; j < 8; j++)
#pragma unroll
                for (int e = 0; e < 4; e++) sc[j][e] = 0.f;

#pragma unroll
            for (int s = 0; s < 4; s++) {
#pragma unroll
                for (int jp = 0; jp < 4; jp++) {
                    uint32_t bh[4];
                    ldsm4(bh, skh +
                          (uint32_t)((jp*16 + kb_r)*FLD + s*16 + kb_c)*2);
                    mma_f16(sc[2*jp  ], qa[s], bh);
                    mma_f16(sc[2*jp+1], qa[s], bh + 2);
                }
            }

            // ---- scale (exp2 domain) + causal mask + online softmax ----
            const bool diag = (kb >= 2*qb);
            float mx0 = NEG_INF, mx1 = NEG_INF;
#pragma unroll
            for (int j = 0; j < 8; j++) {
                const int c0 = kb*64 + j*8 + qd2, c1 = c0 + 1;
                float s0 = sc[j][0]*SC_SCALE, s1 = sc[j][1]*SC_SCALE;
                float s2 = sc[j][2]*SC_SCALE, s3 = sc[j][3]*SC_SCALE;
                if (diag) {
                    if (c0 > grow0) s0 = NEG_INF;
                    if (c1 > grow0) s1 = NEG_INF;
                    if (c0 > grow1) s2 = NEG_INF;
                    if (c1 > grow1) s3 = NEG_INF;
                }
                sc[j][0] = s0; sc[j][1] = s1; sc[j][2] = s2; sc[j][3] = s3;
                mx0 = fmaxf(mx0, fmaxf(s0, s1));
                mx1 = fmaxf(mx1, fmaxf(s2, s3));
            }
            mx0 = fmaxf(mx0, __shfl_xor_sync(0xffffffffu, mx0, 1));
            mx0 = fmaxf(mx0, __shfl_xor_sync(0xffffffffu, mx0, 2));
            mx1 = fmaxf(mx1, __shfl_xor_sync(0xffffffffu, mx1, 1));
            mx1 = fmaxf(mx1, __shfl_xor_sync(0xffffffffu, mx1, 2));

            const float mn0 = fmaxf(m0, mx0), mn1 = fmaxf(m1, mx1);
            const float al0 = exp2f(m0 - mn0), al1 = exp2f(m1 - mn1);
            m0 = mn0; m1 = mn1;

            float s0sum = 0.f, s1sum = 0.f;
#pragma unroll
            for (int j = 0; j < 8; j++) {
                const float p0 = exp2f(sc[j][0] - mn0);
                const float p1 = exp2f(sc[j][1] - mn0);
                const float p2 = exp2f(sc[j][2] - mn1);
                const float p3 = exp2f(sc[j][3] - mn1);
                sc[j][0] = p0; sc[j][1] = p1; sc[j][2] = p2; sc[j][3] = p3;
                s0sum += p0 + p1; s1sum += p2 + p3;
            }
            s0sum += __shfl_xor_sync(0xffffffffu, s0sum, 1);
            s0sum += __shfl_xor_sync(0xffffffffu, s0sum, 2);
            s1sum += __shfl_xor_sync(0xffffffffu, s1sum, 1);
            s1sum += __shfl_xor_sync(0xffffffffu, s1sum, 2);
            l0 = l0 * al0 + s0sum;
            l1 = l1 * al1 + s1sum;

#pragma unroll
            for (int j = 0; j < 8; j++) {
                o[j][0] *= al0; o[j][1] *= al0;
                o[j][2] *= al1; o[j][3] *= al1;
            }

            // ---- o += P @ V ----
#pragma unroll
            for (int s = 0; s < 4; s++) {
                uint32_t a[4];
                a[0] = h2_as_u32(__floats2half2_rn(sc[2*s  ][0], sc[2*s  ][1]));
                a[1] = h2_as_u32(__floats2half2_rn(sc[2*s  ][2], sc[2*s  ][3]));
                a[2] = h2_as_u32(__floats2half2_rn(sc[2*s+1][0], sc[2*s+1][1]));
                a[3] = h2_as_u32(__floats2half2_rn(sc[2*s+1][2], sc[2*s+1][3]));
#pragma unroll
                for (int jp = 0; jp < 4; jp++) {
                    uint32_t bv[4];
                    ldsm4t(bv, svb + (uint32_t)((s*16 + v_r)*FLD + jp*16 + v_c)*2);
                    mma_f16(o[2*jp  ], a, bv);
                    mma_f16(o[2*jp+1], a, bv + 2);
                }
            }
        }
        if (kb + 2 <= kbmax) issue_kv(kb + 2);
    }

    // ---- epilogue ----
    const float inv0 = 1.f / l0, inv1 = 1.f / l1;
    const size_t r1 = qrow0 + 16*w + g;
    const size_t r2 = r1 + 8;
#pragma unroll
    for (int j = 0; j < 8; j++) {
        const int col = hc + j*8 + qd2;
        *(__half2*)(Ch + r1*DD + col) =
            __floats2half2_rn(o[j][0]*inv0, o[j][1]*inv0);
        *(__half2*)(Ch + r2*DD + col) =
            __floats2half2_rn(o[j][2]*inv1, o[j][3]*inv1);
    }
}

// ---------------------------------------------------------------------------
extern "C" void kernel_launch(void* const* d_in, const int* in_sizes, int n_in,
                              void* d_out, int out_size)
{
    const float* x  = (const float*)d_in[0];
    const float* Wq = (const float*)d_in[1];
    const float* Wk = (const float*)d_in[2];
    const float* Wv = (const float*)d_in[3];
    const float* Wo = (const float*)d_in[4];
    const float* bo = (const float*)d_in[5];
    float* out = (float*)d_out;

    __half *xh, *qh, *kh, *vh, *ch, *wh;
    cudaGetSymbolAddress((void**)&xh, g_xh);
    cudaGetSymbolAddress((void**)&qh, g_qh);
    cudaGetSymbolAddress((void**)&kh, g_kh);
    cudaGetSymbolAddress((void**)&vh, g_vh);
    cudaGetSymbolAddress((void**)&ch, g_ch);
    cudaGetSymbolAddress((void**)&wh, g_wh);

    cudaFuncSetAttribute(gemm_fused,
                         cudaFuncAttributeMaxDynamicSharedMemorySize, GEMM_SMEM);
    cudaFuncSetAttribute(flash_mma,
                         cudaFuncAttributeMaxDynamicSharedMemorySize, FLASH_SMEM);

    // weight transpose + fp16 convert
    dim3 wb(32, 8), wg(DD/32, DD/32, 4);
    wtrans4_kernel<<<wg, wb>>>(Wq, Wk, Wv, Wo, wh);

    // x -> fp16
    const int n4 = MROWS * DD / 4;
    xhalf_kernel<<<n4 / 256, 256>>>((const float4*)x, (__half2*)xh, n4);

    // fused QKV projections
    dim3 gq(3 * DD / 128, MROWS / 128);   // (24, 64)
    gemm_fused<<<gq, 256, GEMM_SMEM>>>(xh, wh, nullptr,
                                       qh, kh, vh, nullptr, 0);

    // attention
    dim3 gf(SS / 128, NH, BB);            // (16, 16, 4)
    flash_mma<<<gf, 256, FLASH_SMEM>>>(qh, kh, vh, ch);

    // output projection + bias
    dim3 go(DD / 128, MROWS / 128);       // (8, 64)
    gemm_fused<<<go, 256, GEMM_SMEM>>>(ch, wh, bo,
                                       nullptr, nullptr, nullptr, out, 3);
}

// round 12
// speedup vs baseline: 11.0121x; 1.0330x over previous
#include <cuda_runtime.h>
#include <cuda_bf16.h>
#include <cuda_fp16.h>
#include <math.h>
#include <stdint.h>

#define BB 4
#define SS 2048
#define DD 1024
#define NH 16
#define HDIM 64
#define MROWS (BB*SS)   /* 8192 */

#define SC_SCALE 0.180336880f   /* 0.125 * log2(e), folded into Q projection */

// ---------------- scratch (__device__ globals; allocs forbidden) ------------
__device__ __half g_xh[MROWS*DD];
__device__ __half g_qh[MROWS*DD];
__device__ __half g_kh[MROWS*DD];
__device__ __half g_vh[MROWS*DD];
__device__ __half g_ch[MROWS*DD];
__device__ __half g_wh[4][DD*DD];   // transposed fp16: [Wq, Wk, Wv, Wo]

// ---------------- ptx helpers -------------------------------------------------
static __device__ __forceinline__ void mma_f16(float* c, const uint32_t* a,
                                               const uint32_t* b) {
    asm volatile(
        "mma.sync.aligned.m16n8k16.row.col.f32.f16.f16.f32 "
        "{%0,%1,%2,%3}, {%4,%5,%6,%7}, {%8,%9}, {%0,%1,%2,%3};"
        : "+f"(c[0]), "+f"(c[1]), "+f"(c[2]), "+f"(c[3])
        : "r"(a[0]), "r"(a[1]), "r"(a[2]), "r"(a[3]), "r"(b[0]), "r"(b[1]));
}
static __device__ __forceinline__ void ldsm4(uint32_t* r, uint32_t a) {
    asm volatile("ldmatrix.sync.aligned.m8n8.x4.shared.b16 {%0,%1,%2,%3}, [%4];"
                 : "=r"(r[0]), "=r"(r[1]), "=r"(r[2]), "=r"(r[3]) : "r"(a));
}
static __device__ __forceinline__ void ldsm4t(uint32_t* r, uint32_t a) {
    asm volatile("ldmatrix.sync.aligned.m8n8.x4.trans.shared.b16 {%0,%1,%2,%3}, [%4];"
                 : "=r"(r[0]), "=r"(r[1]), "=r"(r[2]), "=r"(r[3]) : "r"(a));
}
static __device__ __forceinline__ uint32_t s2u(const void* p) {
    uint32_t a;
    asm("{ .reg .u64 t; cvta.to.shared.u64 t, %1; cvt.u32.u64 %0, t; }"
        : "=r"(a) : "l"(p));
    return a;
}
static __device__ __forceinline__ void cpa16(uint32_t dst, const void* src) {
    asm volatile("cp.async.cg.shared.global [%0], [%1], 16;"
                 :: "r"(dst), "l"(src));
}
static __device__ __forceinline__ void cp_commit() {
    asm volatile("cp.async.commit_group;");
}
template<int N>
static __device__ __forceinline__ void cp_wait() {
    asm volatile("cp.async.wait_group %0;" :: "n"(N));
}
// exp2 of two fp32 values via packed fp16: result is a ready PV A-fragment half2
static __device__ __forceinline__ uint32_t exp2_f16x2(float lo, float hi) {
    uint32_t h, r;
    asm("cvt.rn.f16x2.f32 %0, %1, %2;" : "=r"(h) : "f"(hi), "f"(lo));
    asm("ex2.approx.f16x2 %0, %1;" : "=r"(r) : "r"(h));
    return r;
}

// ---------------- convert / transpose kernels --------------------------------
__global__ void xhalf_kernel(const float4* __restrict__ x,
                             __half2* __restrict__ xh, int n4)
{
    int i = blockIdx.x * blockDim.x + threadIdx.x;
    if (i >= n4) return;
    float4 v = x[i];
    xh[2*i]   = __floats2half2_rn(v.x, v.y);
    xh[2*i+1] = __floats2half2_rn(v.z, v.w);
}

__global__ void wtrans4_kernel(const float* __restrict__ W0,
                               const float* __restrict__ W1,
                               const float* __restrict__ W2,
                               const float* __restrict__ W3,
                               __half* __restrict__ wh)
{
    __shared__ float t[32][33];
    const float* Ws[4] = {W0, W1, W2, W3};
    const int z = blockIdx.z;
    const float* W = Ws[z];
    __half* th = wh + (size_t)z * DD * DD;

    const int n0 = blockIdx.x * 32, k0 = blockIdx.y * 32;
    const int tx = threadIdx.x, ty = threadIdx.y;
#pragma unroll
    for (int i = 0; i < 32; i += 8)
        t[ty + i][tx] = W[(size_t)(k0 + ty + i) * DD + n0 + tx];
    __syncthreads();
#pragma unroll
    for (int i = 0; i < 32; i += 8) {
        size_t o = (size_t)(n0 + ty + i) * DD + k0 + tx;
        th[o] = __float2half_rn(t[tx][ty + i]);
    }
}

// ---------------- fused fp16 mma.sync GEMM ------------------------------------
// sel = sel_base + blockIdx.x/8:
//   0: x@Wq*SC_SCALE -> qh   1: x@Wk -> kh   2: x@Wv -> vh
//   3: ctx@Wo+bias -> outF
#define ALD2 72
#define G_MAT2 (128*ALD2)
#define NSTG 16
#define GEMM_SMEM (2 * 3 * G_MAT2 * 2)          /* 110592 bytes */

__global__ __launch_bounds__(256, 2)
void gemm_fused(const __half* __restrict__ A, const __half* __restrict__ wh,
                const float* __restrict__ bias,
                __half* __restrict__ qh, __half* __restrict__ kh,
                __half* __restrict__ vh, float* __restrict__ outF,
                int sel_base)
{
    extern __shared__ char smg[];
    const uint32_t asu = s2u(smg);
    const uint32_t bsu = asu + 3 * G_MAT2 * 2;

    const int t = threadIdx.x;
    const int wid = t >> 5, lane = t & 31;
    const int wm = wid & 1, wn = wid >> 1;
    const int g = lane >> 2, qd = lane & 3;
    const int qd2 = qd * 2;
    const int sel = sel_base + (blockIdx.x >> 3);
    const int n0 = (blockIdx.x & 7) * 128;
    const int m0 = blockIdx.y * 128;

    const __half* B = wh + (size_t)sel * DD * DD;

    const int ld_row = t >> 3;
    const int ld_col = (t & 7) * 8;

    const int a_r = wm*64 + (lane & 15);
    const int a_c = (lane >> 4) * 8;
    const int b_r = wn*32 + (lane & 7) + ((lane >> 4) << 3);
    const int b_c = ((lane >> 3) & 1) * 8;

    float acc[4][4][4];
#pragma unroll
    for (int i = 0; i < 4; i++)
#pragma unroll
        for (int j = 0; j < 4; j++)
#pragma unroll
            for (int e = 0; e < 4; e++) acc[i][j][e] = 0.f;

    auto issue = [&](int s) {
        const int st = s % 3;
        const int kc = s * 64;
#pragma unroll
        for (int i = 0; i < 4; i++) {
            const int row = ld_row + i*32;
            const uint32_t so = (uint32_t)(st*G_MAT2 + row*ALD2 + ld_col) * 2;
            cpa16(asu + so, A + (size_t)(m0 + row) * DD + kc + ld_col);
            cpa16(bsu + so, B + (size_t)(n0 + row) * DD + kc + ld_col);
        }
        cp_commit();
    };

    issue(0);
    issue(1);

    for (int s = 0; s < NSTG; s++) {
        const int st = s % 3;
        if (s == NSTG - 1) cp_wait<0>();
        else               cp_wait<1>();
        __syncthreads();

        const uint32_t ab = asu + (uint32_t)(st*G_MAT2)*2;
        const uint32_t bb = bsu + (uint32_t)(st*G_MAT2)*2;
#pragma unroll
        for (int kk = 0; kk < 4; kk++) {
            uint32_t a[4][4], b4[2][4];
#pragma unroll
            for (int i = 0; i < 4; i++)
                ldsm4(a[i], ab + (uint32_t)((a_r + i*16)*ALD2 + kk*16 + a_c)*2);
#pragma unroll
            for (int jp = 0; jp < 2; jp++)
                ldsm4(b4[jp], bb + (uint32_t)((b_r + jp*16)*ALD2 + kk*16 + b_c)*2);
#pragma unroll
            for (int i = 0; i < 4; i++)
#pragma unroll
                for (int j = 0; j < 4; j++)
                    mma_f16(acc[i][j], a[i], &b4[j >> 1][(j & 1) * 2]);
        }
        if (s + 2 < NSTG) issue(s + 2);
    }

    // epilogue
    __half* oH = (sel == 0) ? qh : ((sel == 1) ? kh : vh);
    const float f = (sel == 0) ? SC_SCALE : 1.0f;   // fold softmax scale into Q
#pragma unroll
    for (int i = 0; i < 4; i++) {
        const int r1 = m0 + wm*64 + i*16 + g;
        const int r2 = r1 + 8;
#pragma unroll
        for (int j = 0; j < 4; j++) {
            const int col = n0 + wn*32 + j*8 + qd2;
            const float v0 = acc[i][j][0], v1 = acc[i][j][1];
            const float v2 = acc[i][j][2], v3 = acc[i][j][3];
            if (sel == 3) {
                float2 o1, o2;
                o1.x = v0 + bias[col]; o1.y = v1 + bias[col+1];
                o2.x = v2 + bias[col]; o2.y = v3 + bias[col+1];
                *(float2*)(outF + (size_t)r1 * DD + col) = o1;
                *(float2*)(outF + (size_t)r2 * DD + col) = o2;
            } else {
                *(__half2*)(oH + (size_t)r1 * DD + col) =
                    __floats2half2_rn(v0*f, v1*f);
                *(__half2*)(oH + (size_t)r2 * DD + col) =
                    __floats2half2_rn(v2*f, v3*f);
            }
        }
    }
}

// ---------------- causal flash attention (fp16 mma, f16x2 softmax) ------------
// 128 q-rows x 64-key tiles, 256 threads, 2 CTAs/SM. Q single fp16 (pre-scaled)
// in regs; softmax: exp2 in packed fp16, row-sum via ones-column MMA (exact,
// consistent with the fp16 P used in PV).
#define FLD 72
#define ST_ONE  (64*FLD*2)                    /* 9216  */
#define ST_BYTES (2*ST_ONE)                   /* 18432: K + V per stage */
#define FLASH_SMEM (3*ST_BYTES)               /* 55296 */

__global__ __launch_bounds__(256, 2)
void flash_mma(const __half* __restrict__ Qh, const __half* __restrict__ Kh,
               const __half* __restrict__ Vh, __half* __restrict__ Ch)
{
    extern __shared__ char smc[];
    const uint32_t smu = s2u(smc);

    const int t = threadIdx.x;
    const int w = t >> 5, lane = t & 31;
    const int g = lane >> 2, qd = lane & 3;
    const int qd2 = qd * 2;
    const int qb = (gridDim.x - 1) - blockIdx.x;
    const int h = blockIdx.y, b = blockIdx.z;

    const size_t qrow0 = (size_t)b * SS + qb * 128;
    const size_t krow0 = (size_t)b * SS;
    const int hc = h * HDIM;
    const int kbmax = 2*qb + 1;

    const int qa_r = 16*w + (lane & 15);
    const int qa_c = (lane >> 4) * 8;
    const int kb_r = (lane & 7) + ((lane >> 4) << 3);
    const int kb_c = ((lane >> 3) & 1) * 8;
    const int v_r  = (lane & 7) + (((lane >> 3) & 1) << 3);
    const int v_c  = (lane >> 4) * 8;

    // ---- Q staging: 128 rows x 128 B = 1024 chunks of 16B (4 sweeps) ----
#pragma unroll
    for (int i = 0; i < 4; i++) {
        const int idx = t + 256*i;              // 0..1023
        const int row = idx >> 3, col = (idx & 7) * 8;
        cpa16(smu + (uint32_t)(row*FLD + col)*2, Qh + (qrow0 + row)*DD + hc + col);
    }
    cp_commit();
    cp_wait<0>();
    __syncthreads();

    uint32_t qa[4][4];
#pragma unroll
    for (int s = 0; s < 4; s++)
        ldsm4(qa[s], smu + (uint32_t)(qa_r*FLD + s*16 + qa_c)*2);
    __syncthreads();

    auto issue_kv = [&](int kb) {
        const uint32_t sb = smu + (kb % 3)*ST_BYTES;
#pragma unroll
        for (int i = 0; i < 2; i++) {
            const int idx = t + 256*i;
            const int row = idx >> 3, col = (idx & 7) * 8;
            const uint32_t so = (uint32_t)(row*FLD + col) * 2;
            const size_t gr = (krow0 + kb*64 + row)*DD + hc + col;
            cpa16(sb + so,          Kh + gr);
            cpa16(sb + ST_ONE + so, Vh + gr);
        }
        cp_commit();
    };
    issue_kv(0);
    issue_kv(1);

    float sc[8][4], o[8][4];
#pragma unroll
    for (int j = 0; j < 8; j++)
#pragma unroll
        for (int e = 0; e < 4; e++) o[j][e] = 0.f;
    const float NEG_INF = __int_as_float(0xff800000u);
    float m0 = NEG_INF, m1 = NEG_INF, l0 = 0.f, l1 = 0.f;

    const int grow0 = qb*128 + 16*w + g;
    const int grow1 = grow0 + 8;
    const int wrow_max = qb*128 + 16*w + 15;

    const uint32_t ones2 = 0x3C003C00u;       // half2(1, 1)
    const uint32_t onesb[2] = {ones2, ones2};

    for (int kb = 0; kb <= kbmax; kb++) {
        const int st = kb % 3;
        if (kb == kbmax) cp_wait<0>();
        else             cp_wait<1>();
        __syncthreads();

        const bool active = (kb*64 <= wrow_max);
        if (active) {
            const uint32_t skh = smu + st*ST_BYTES;
            const uint32_t svb = skh + ST_ONE;

#pragma unroll
            for (int j = 0; j < 8; j++)
#pragma unroll
                for (int e = 0; e < 4; e++) sc[j][e] = 0.f;

#pragma unroll
            for (int s = 0; s < 4; s++) {
#pragma unroll
                for (int jp = 0; jp < 4; jp++) {
                    uint32_t bh[4];
                    ldsm4(bh, skh +
                          (uint32_t)((jp*16 + kb_r)*FLD + s*16 + kb_c)*2);
                    mma_f16(sc[2*jp  ], qa[s], bh);
                    mma_f16(sc[2*jp+1], qa[s], bh + 2);
                }
            }

            // ---- causal mask + row max (scale pre-folded into Q) ----
            const bool diag = (kb >= 2*qb);
            float mx0 = NEG_INF, mx1 = NEG_INF;
#pragma unroll
            for (int j = 0; j < 8; j++) {
                if (diag) {
                    const int c0 = kb*64 + j*8 + qd2, c1 = c0 + 1;
                    if (c0 > grow0) sc[j][0] = NEG_INF;
                    if (c1 > grow0) sc[j][1] = NEG_INF;
                    if (c0 > grow1) sc[j][2] = NEG_INF;
                    if (c1 > grow1) sc[j][3] = NEG_INF;
                }
                mx0 = fmaxf(mx0, fmaxf(sc[j][0], sc[j][1]));
                mx1 = fmaxf(mx1, fmaxf(sc[j][2], sc[j][3]));
            }
            mx0 = fmaxf(mx0, __shfl_xor_sync(0xffffffffu, mx0, 1));
            mx0 = fmaxf(mx0, __shfl_xor_sync(0xffffffffu, mx0, 2));
            mx1 = fmaxf(mx1, __shfl_xor_sync(0xffffffffu, mx1, 1));
            mx1 = fmaxf(mx1, __shfl_xor_sync(0xffffffffu, mx1, 2));

            const float mn0 = fmaxf(m0, mx0), mn1 = fmaxf(m1, mx1);
            const float al0 = exp2f(m0 - mn0), al1 = exp2f(m1 - mn1);
            m0 = mn0; m1 = mn1;

            // ---- p = exp2(s - m) in packed fp16 (ready PV fragments) ----
            uint32_t pf[8][2];
#pragma unroll
            for (int j = 0; j < 8; j++) {
                pf[j][0] = exp2_f16x2(sc[j][0] - mn0, sc[j][1] - mn0);
                pf[j][1] = exp2_f16x2(sc[j][2] - mn1, sc[j][3] - mn1);
            }

            // ---- rescale o ----
#pragma unroll
            for (int j = 0; j < 8; j++) {
                o[j][0] *= al0; o[j][1] *= al0;
                o[j][2] *= al1; o[j][3] *= al1;
            }

            // ---- PV + row-sum (ones column) ----
            float lacc[4] = {0.f, 0.f, 0.f, 0.f};
#pragma unroll
            for (int s = 0; s < 4; s++) {
                uint32_t a[4];
                a[0] = pf[2*s  ][0]; a[1] = pf[2*s  ][1];
                a[2] = pf[2*s+1][0]; a[3] = pf[2*s+1][1];
                mma_f16(lacc, a, onesb);       // exact fp32 row sums of fp16 P
#pragma unroll
                for (int jp = 0; jp < 4; jp++) {
                    uint32_t bv[4];
                    ldsm4t(bv, svb + (uint32_t)((s*16 + v_r)*FLD + jp*16 + v_c)*2);
                    mma_f16(o[2*jp  ], a, bv);
                    mma_f16(o[2*jp+1], a, bv + 2);
                }
            }
            l0 = l0 * al0 + lacc[0];
            l1 = l1 * al1 + lacc[2];
        }
        if (kb + 2 <= kbmax) issue_kv(kb + 2);
    }

    // ---- epilogue ----
    const float inv0 = 1.f / l0, inv1 = 1.f / l1;
    const size_t r1 = qrow0 + 16*w + g;
    const size_t r2 = r1 + 8;
#pragma unroll
    for (int j = 0; j < 8; j++) {
        const int col = hc + j*8 + qd2;
        *(__half2*)(Ch + r1*DD + col) =
            __floats2half2_rn(o[j][0]*inv0, o[j][1]*inv0);
        *(__half2*)(Ch + r2*DD + col) =
            __floats2half2_rn(o[j][2]*inv1, o[j][3]*inv1);
    }
}

// ---------------------------------------------------------------------------
extern "C" void kernel_launch(void* const* d_in, const int* in_sizes, int n_in,
                              void* d_out, int out_size)
{
    const float* x  = (const float*)d_in[0];
    const float* Wq = (const float*)d_in[1];
    const float* Wk = (const float*)d_in[2];
    const float* Wv = (const float*)d_in[3];
    const float* Wo = (const float*)d_in[4];
    const float* bo = (const float*)d_in[5];
    float* out = (float*)d_out;

    __half *xh, *qh, *kh, *vh, *ch, *wh;
    cudaGetSymbolAddress((void**)&xh, g_xh);
    cudaGetSymbolAddress((void**)&qh, g_qh);
    cudaGetSymbolAddress((void**)&kh, g_kh);
    cudaGetSymbolAddress((void**)&vh, g_vh);
    cudaGetSymbolAddress((void**)&ch, g_ch);
    cudaGetSymbolAddress((void**)&wh, g_wh);

    cudaFuncSetAttribute(gemm_fused,
                         cudaFuncAttributeMaxDynamicSharedMemorySize, GEMM_SMEM);
    cudaFuncSetAttribute(flash_mma,
                         cudaFuncAttributeMaxDynamicSharedMemorySize, FLASH_SMEM);

    // weight transpose + fp16 convert
    dim3 wb(32, 8), wg(DD/32, DD/32, 4);
    wtrans4_kernel<<<wg, wb>>>(Wq, Wk, Wv, Wo, wh);

    // x -> fp16
    const int n4 = MROWS * DD / 4;
    xhalf_kernel<<<n4 / 256, 256>>>((const float4*)x, (__half2*)xh, n4);

    // fused QKV projections
    dim3 gq(3 * DD / 128, MROWS / 128);   // (24, 64)
    gemm_fused<<<gq, 256, GEMM_SMEM>>>(xh, wh, nullptr,
                                       qh, kh, vh, nullptr, 0);

    // attention
    dim3 gf(SS / 128, NH, BB);            // (16, 16, 4)
    flash_mma<<<gf, 256, FLASH_SMEM>>>(qh, kh, vh, ch);

    // output projection + bias
    dim3 go(DD / 128, MROWS / 128);       // (8, 64)
    gemm_fused<<<go, 256, GEMM_SMEM>>>(ch, wh, bo,
                                       nullptr, nullptr, nullptr, out, 3);
}